// round 1
// baseline (speedup 1.0000x reference)
#include <cuda_runtime.h>
#include <cstdint>

// ---------------------------------------------------------------------------
// MultiHeadAttention fp32 baseline for GB300 (sm_103a)
//   Q = x Wq^T + b ; K,V likewise        (NT GEMM, 8192x2048x2048)
//   per g in [0,128): scores = Qg Kg^T / sqrt(2048)   (NT, 1024x1024x128)
//   weights = softmax(scores)  (row softmax, written to d_out tail)
//   attn = weights Vg                                  (NN, 1024x128x1024)
//   out = attn Wo^T + b                                (NT, 8192x2048x2048)
// Inner loop uses packed fma.rn.f32x2 (Blackwell FFMA2, 2x fp32 throughput).
// ---------------------------------------------------------------------------

#define BM 128
#define BN 128
#define BKT 16
#define TM 8
#define TN 8

enum { EPI_NONE = 0, EPI_BIAS = 1, EPI_SCALE = 2 };

static constexpr long long QKV_ELEMS = 8LL * 1024 * 2048;        // 16,777,216
static constexpr long long W_ELEMS   = 128LL * 1024 * 1024;      // 134,217,728

__device__ float g_Q[QKV_ELEMS];
__device__ float g_K[QKV_ELEMS];
__device__ float g_V[QKV_ELEMS];
__device__ float g_ATTN[QKV_ELEMS];
__device__ float g_WSCRATCH[W_ELEMS];

// packed f32x2 fma: c = a*b + c
__device__ __forceinline__ void ffma2(float2& c, const float2 a, const float2 b) {
    union F2U { float2 f; unsigned long long u; };
    F2U au, bu, cu;
    au.f = a; bu.f = b; cu.f = c;
    asm("fma.rn.f32x2 %0, %1, %2, %0;" : "+l"(cu.u) : "l"(au.u), "l"(bu.u));
    c = cu.f;
}

// C[M,N] = A[M,K] * op(B) (+bias / *scale), batched over blockIdx.z.
// BT=true : B is [N,K] row-major (NT gemm, C[m,n] = sum_k A[m,k]*B[n,k])
// BT=false: B is [K,N] row-major (NN gemm)
template <bool BT, int EPI>
__global__ __launch_bounds__(256, 2)
void gemm_kernel(const float* __restrict__ A, const float* __restrict__ B,
                 const float* __restrict__ bias, float* __restrict__ C,
                 int M, int N, int K,
                 long long strideA, long long strideB, long long strideC,
                 float scale)
{
    __shared__ float As[BKT][BM];
    __shared__ float Bs[BKT][BN];

    const int z = blockIdx.z;
    A += (long long)z * strideA;
    B += (long long)z * strideB;
    C += (long long)z * strideC;

    const int tid  = threadIdx.x;
    const int tx   = tid & 15;
    const int ty   = tid >> 4;
    const int row0 = ty * TM;
    const int col0 = tx * TN;

    const int cbm = blockIdx.y * BM;
    const int cbn = blockIdx.x * BN;

    // loader indices
    const int a_row = tid >> 2;            // 0..63 (+64)
    const int a_col = (tid & 3) * 4;       // 0,4,8,12
    const int bn_k  = tid >> 5;            // 0..7 (+8)   (NN path)
    const int bn_n  = (tid & 31) * 4;      // 0..124      (NN path)

    float2 acc[TM][TN / 2];
    #pragma unroll
    for (int i = 0; i < TM; i++)
        #pragma unroll
        for (int j = 0; j < TN / 2; j++)
            acc[i][j] = make_float2(0.f, 0.f);

    for (int kt = 0; kt < K; kt += BKT) {
        // --- load A tile [BM][BKT], store transposed As[k][m] ---
        #pragma unroll
        for (int r = 0; r < 2; r++) {
            const float4 v = *reinterpret_cast<const float4*>(
                &A[(long long)(cbm + a_row + r * 64) * K + kt + a_col]);
            const int m = a_row + r * 64;
            As[a_col + 0][m] = v.x;
            As[a_col + 1][m] = v.y;
            As[a_col + 2][m] = v.z;
            As[a_col + 3][m] = v.w;
        }
        // --- load B tile ---
        if (BT) {
            #pragma unroll
            for (int r = 0; r < 2; r++) {
                const float4 v = *reinterpret_cast<const float4*>(
                    &B[(long long)(cbn + a_row + r * 64) * K + kt + a_col]);
                const int n = a_row + r * 64;
                Bs[a_col + 0][n] = v.x;
                Bs[a_col + 1][n] = v.y;
                Bs[a_col + 2][n] = v.z;
                Bs[a_col + 3][n] = v.w;
            }
        } else {
            #pragma unroll
            for (int r = 0; r < 2; r++) {
                const float4 v = *reinterpret_cast<const float4*>(
                    &B[(long long)(kt + bn_k + r * 8) * N + cbn + bn_n]);
                *reinterpret_cast<float4*>(&Bs[bn_k + r * 8][bn_n]) = v;
            }
        }
        __syncthreads();

        // --- compute ---
        #pragma unroll
        for (int k = 0; k < BKT; k++) {
            const float4 a0 = *reinterpret_cast<const float4*>(&As[k][row0]);
            const float4 a1 = *reinterpret_cast<const float4*>(&As[k][row0 + 4]);
            const float4 b0 = *reinterpret_cast<const float4*>(&Bs[k][col0]);
            const float4 b1 = *reinterpret_cast<const float4*>(&Bs[k][col0 + 4]);
            const float a[TM] = {a0.x, a0.y, a0.z, a0.w, a1.x, a1.y, a1.z, a1.w};
            float2 bp[4];
            bp[0] = make_float2(b0.x, b0.y);
            bp[1] = make_float2(b0.z, b0.w);
            bp[2] = make_float2(b1.x, b1.y);
            bp[3] = make_float2(b1.z, b1.w);
            #pragma unroll
            for (int i = 0; i < TM; i++) {
                const float2 ad = make_float2(a[i], a[i]);
                #pragma unroll
                for (int j = 0; j < 4; j++)
                    ffma2(acc[i][j], ad, bp[j]);
            }
        }
        __syncthreads();
    }

    // --- epilogue ---
    float bb[TN];
    if (EPI == EPI_BIAS) {
        const float4 v0 = *reinterpret_cast<const float4*>(&bias[cbn + col0]);
        const float4 v1 = *reinterpret_cast<const float4*>(&bias[cbn + col0 + 4]);
        bb[0] = v0.x; bb[1] = v0.y; bb[2] = v0.z; bb[3] = v0.w;
        bb[4] = v1.x; bb[5] = v1.y; bb[6] = v1.z; bb[7] = v1.w;
    }
    #pragma unroll
    for (int i = 0; i < TM; i++) {
        float o[TN] = {acc[i][0].x, acc[i][0].y, acc[i][1].x, acc[i][1].y,
                       acc[i][2].x, acc[i][2].y, acc[i][3].x, acc[i][3].y};
        #pragma unroll
        for (int j = 0; j < TN; j++) {
            if (EPI == EPI_SCALE) o[j] *= scale;
            if (EPI == EPI_BIAS)  o[j] += bb[j];
        }
        float* cp = &C[(long long)(cbm + row0 + i) * N + cbn + col0];
        *reinterpret_cast<float4*>(cp)     = make_float4(o[0], o[1], o[2], o[3]);
        *reinterpret_cast<float4*>(cp + 4) = make_float4(o[4], o[5], o[6], o[7]);
    }
}

// Row softmax over rows of length 1024 (one block per row, 256 threads x float4)
__global__ __launch_bounds__(256)
void softmax1024(float* __restrict__ w)
{
    __shared__ float smax[8];
    __shared__ float ssum[8];
    float* row = w + (long long)blockIdx.x * 1024;
    const int tid = threadIdx.x;

    float4 v = reinterpret_cast<float4*>(row)[tid];
    float m = fmaxf(fmaxf(v.x, v.y), fmaxf(v.z, v.w));
    #pragma unroll
    for (int o = 16; o > 0; o >>= 1)
        m = fmaxf(m, __shfl_xor_sync(0xffffffffu, m, o));
    if ((tid & 31) == 0) smax[tid >> 5] = m;
    __syncthreads();
    const float bm = fmaxf(fmaxf(fmaxf(smax[0], smax[1]), fmaxf(smax[2], smax[3])),
                           fmaxf(fmaxf(smax[4], smax[5]), fmaxf(smax[6], smax[7])));

    v.x = expf(v.x - bm);
    v.y = expf(v.y - bm);
    v.z = expf(v.z - bm);
    v.w = expf(v.w - bm);
    float s = v.x + v.y + v.z + v.w;
    #pragma unroll
    for (int o = 16; o > 0; o >>= 1)
        s += __shfl_xor_sync(0xffffffffu, s, o);
    if ((tid & 31) == 0) ssum[tid >> 5] = s;
    __syncthreads();
    const float tot = ssum[0] + ssum[1] + ssum[2] + ssum[3] +
                      ssum[4] + ssum[5] + ssum[6] + ssum[7];
    const float inv = 1.0f / tot;
    v.x *= inv; v.y *= inv; v.z *= inv; v.w *= inv;
    reinterpret_cast<float4*>(row)[tid] = v;
}

extern "C" void kernel_launch(void* const* d_in, const int* in_sizes, int n_in,
                              void* d_out, int out_size)
{
    (void)in_sizes; (void)n_in;
    const float* query = (const float*)d_in[0];
    const float* key   = (const float*)d_in[1];
    const float* value = (const float*)d_in[2];
    const float* Wq_w  = (const float*)d_in[3];
    const float* Wq_b  = (const float*)d_in[4];
    const float* Wk_w  = (const float*)d_in[5];
    const float* Wk_b  = (const float*)d_in[6];
    const float* Wv_w  = (const float*)d_in[7];
    const float* Wv_b  = (const float*)d_in[8];
    const float* Wo_w  = (const float*)d_in[9];
    const float* Wo_b  = (const float*)d_in[10];

    float *Qb, *Kb, *Vb, *Ab, *Ws;
    cudaGetSymbolAddress((void**)&Qb, g_Q);
    cudaGetSymbolAddress((void**)&Kb, g_K);
    cudaGetSymbolAddress((void**)&Vb, g_V);
    cudaGetSymbolAddress((void**)&Ab, g_ATTN);
    cudaGetSymbolAddress((void**)&Ws, g_WSCRATCH);

    float* out = (float*)d_out;
    // reference returns (out, weights); if the harness buffer holds both,
    // write weights directly into d_out's tail, else to scratch.
    float* weights = ((long long)out_size >= QKV_ELEMS + W_ELEMS)
                         ? out + QKV_ELEMS : Ws;

    const int M = 8192, D = 2048;
    const float inv_sqrt_d = 0.022097086912079608f;  // 1/sqrt(2048)

    dim3 blk(256);
    dim3 gproj(D / BN, M / BM, 1);     // (16, 64, 1)
    dim3 gsc(1024 / BN, 1024 / BM, 128);
    dim3 gpv(128 / BN, 1024 / BM, 128);

    // projections
    gemm_kernel<true, EPI_BIAS><<<gproj, blk>>>(query, Wq_w, Wq_b, Qb,
                                                M, D, D, 0, 0, 0, 1.f);
    gemm_kernel<true, EPI_BIAS><<<gproj, blk>>>(key,   Wk_w, Wk_b, Kb,
                                                M, D, D, 0, 0, 0, 1.f);
    gemm_kernel<true, EPI_BIAS><<<gproj, blk>>>(value, Wv_w, Wv_b, Vb,
                                                M, D, D, 0, 0, 0, 1.f);
    // scores = Q K^T / sqrt(D), per contiguous slab g (stride 1024*128)
    gemm_kernel<true, EPI_SCALE><<<gsc, blk>>>(Qb, Kb, nullptr, weights,
                                               1024, 1024, 128,
                                               131072LL, 131072LL, 1048576LL,
                                               inv_sqrt_d);
    // softmax rows (128*1024 rows of 1024)
    softmax1024<<<dim3(131072), blk>>>(weights);
    // attn = weights @ V
    gemm_kernel<false, EPI_NONE><<<gpv, blk>>>(weights, Vb, nullptr, Ab,
                                               1024, 128, 1024,
                                               1048576LL, 131072LL, 131072LL,
                                               1.f);
    // out = attn @ Wo^T + b
    gemm_kernel<true, EPI_BIAS><<<gproj, blk>>>(Ab, Wo_w, Wo_b, out,
                                                M, D, D, 0, 0, 0, 1.f);
}

// round 3
// speedup vs baseline: 1.7860x; 1.7860x over previous
#include <cuda_runtime.h>
#include <cuda_bf16.h>
#include <cstdint>

// ---------------------------------------------------------------------------
// MultiHeadAttention on GB300 (sm_103a) — tensor cores via arch-portable
// mma.sync.m16n8k16 bf16 (harness PTX target is compute_103; tcgen05 is not
// available there). fp32 operands split into bf16 hi+lo; 3 MMA terms
// (hi*hi + hi*lo + lo*hi) accumulated in fp32 registers -> ~4e-6 rel err.
// GEMM: 128x128 tile, BK=32, cp.async double buffer, ldmatrix.x4, 8 warps.
// ---------------------------------------------------------------------------

using bf16 = __nv_bfloat16;

static constexpr long long QKV_ELEMS = 8LL * 1024 * 2048;    // 16,777,216
static constexpr long long W_ELEMS   = 128LL * 1024 * 1024;  // 134,217,728
static constexpr long long WW_ELEMS  = 2048LL * 2048;        // 4,194,304

__device__ bf16 g_xqh[QKV_ELEMS], g_xql[QKV_ELEMS];
__device__ bf16 g_xkh[QKV_ELEMS], g_xkl[QKV_ELEMS];
__device__ bf16 g_xvh[QKV_ELEMS], g_xvl[QKV_ELEMS];
__device__ bf16 g_wqh[WW_ELEMS], g_wql[WW_ELEMS];
__device__ bf16 g_wkh[WW_ELEMS], g_wkl[WW_ELEMS];
__device__ bf16 g_wvh[WW_ELEMS], g_wvl[WW_ELEMS];
__device__ bf16 g_woh[WW_ELEMS], g_wol[WW_ELEMS];
__device__ bf16 g_Qh[QKV_ELEMS], g_Ql[QKV_ELEMS];
__device__ bf16 g_Kh[QKV_ELEMS], g_Kl[QKV_ELEMS];
__device__ bf16 g_Vh[QKV_ELEMS], g_Vl[QKV_ELEMS];
__device__ bf16 g_Vth[QKV_ELEMS], g_Vtl[QKV_ELEMS];
__device__ bf16 g_Ph[W_ELEMS], g_Pl[W_ELEMS];
__device__ bf16 g_Ah[QKV_ELEMS], g_Al[QKV_ELEMS];
__device__ float g_WS[W_ELEMS];

// ------------------------- asm helpers --------------------------------------

__device__ __forceinline__ uint32_t smem_u32(const void* p) {
    uint32_t a;
    asm("{ .reg .u64 t; cvta.to.shared.u64 t, %1; cvt.u32.u64 %0, t; }"
        : "=r"(a) : "l"(p));
    return a;
}

__device__ __forceinline__ void cp16(uint32_t dst, const void* src) {
    asm volatile("cp.async.cg.shared.global [%0], [%1], 16;"
                 :: "r"(dst), "l"(src));
}

__device__ __forceinline__ void ldm_x4(uint32_t* r, uint32_t addr) {
    asm volatile("ldmatrix.sync.aligned.m8n8.x4.shared.b16 {%0,%1,%2,%3}, [%4];"
                 : "=r"(r[0]), "=r"(r[1]), "=r"(r[2]), "=r"(r[3]) : "r"(addr));
}

__device__ __forceinline__ void mma16816(float* c, const uint32_t* a,
                                         uint32_t b0, uint32_t b1) {
    asm volatile(
        "mma.sync.aligned.m16n8k16.row.col.f32.bf16.bf16.f32 "
        "{%0,%1,%2,%3}, {%4,%5,%6,%7}, {%8,%9}, {%0,%1,%2,%3};"
        : "+f"(c[0]), "+f"(c[1]), "+f"(c[2]), "+f"(c[3])
        : "r"(a[0]), "r"(a[1]), "r"(a[2]), "r"(a[3]), "r"(b0), "r"(b1));
}

// ------------------------- GEMM ---------------------------------------------
// NT: C[m,n] = sum_k A[m,k] * B[n,k], A/B split bf16 (hi, lo), K-major.
// EPI: 0 = split-bf16 + bias, 1 = f32 * scale, 2 = split-bf16, 3 = f32 + bias

#define STAGE 32768
#define T_AH 0
#define T_AL 8192
#define T_BH 16384
#define T_BL 24576
#define SMEM_TOTAL 69632   // max(2*STAGE, 128*132*4 epilogue staging)

// swizzled in-tile byte offset for (row, 16B-chunk cq)
__device__ __forceinline__ uint32_t swz(int row, int cq) {
    return (uint32_t)(row * 64 + ((cq ^ ((row >> 1) & 3)) << 4));
}

template <int EPI>
__global__ __launch_bounds__(256, 1)
void gemm_mma(const bf16* __restrict__ Ah, const bf16* __restrict__ Al,
              const bf16* __restrict__ Bh, const bf16* __restrict__ Bl,
              const float* __restrict__ bias,
              float* __restrict__ Cf, bf16* __restrict__ Ch, bf16* __restrict__ Cl,
              int K, int lda, int ldb, int ldc,
              long long sA, long long sB, long long sC, float scale)
{
    extern __shared__ char smem[];
    const uint32_t sb = smem_u32(smem);
    const int tid = threadIdx.x;
    const int wid = tid >> 5;
    const int lane = tid & 31;
    const int warpM = wid >> 1;          // 0..3  (m tile 32)
    const int warpN = wid & 1;           // 0..1  (n tile 64)

    const long long z = blockIdx.z;
    Ah += z * sA; Al += z * sA;
    Bh += z * sB; Bl += z * sB;
    if (EPI == 1 || EPI == 3) Cf += z * sC; else { Ch += z * sC; Cl += z * sC; }

    const int m0 = blockIdx.y * 128;
    const int n0 = blockIdx.x * 128;
    const int NS = K >> 5;

    // loader: 512 16B chunks per 8KB tile, 4 tiles, 256 threads -> 8 cp.async
    const int lrow = tid >> 1;                 // rows 0..127
    const int lcq0 = (tid & 1) * 2;            // chunks {0,1} or {2,3}

    auto issue_stage = [&](int s, int buf) {
        const int k0 = s << 5;
        const uint32_t base = sb + buf * STAGE;
        #pragma unroll
        for (int t = 0; t < 2; t++) {
            const int cq = lcq0 + t;
            const uint32_t so = swz(lrow, cq);
            const size_t ga = (size_t)(m0 + lrow) * lda + k0 + cq * 8;
            const size_t gb = (size_t)(n0 + lrow) * ldb + k0 + cq * 8;
            cp16(base + T_AH + so, Ah + ga);
            cp16(base + T_AL + so, Al + ga);
            cp16(base + T_BH + so, Bh + gb);
            cp16(base + T_BL + so, Bl + gb);
        }
        asm volatile("cp.async.commit_group;");
    };

    float acc[2][8][4];
    #pragma unroll
    for (int mt = 0; mt < 2; mt++)
        #pragma unroll
        for (int nt = 0; nt < 8; nt++)
            #pragma unroll
            for (int j = 0; j < 4; j++)
                acc[mt][nt][j] = 0.f;

    const int frow = lane & 15;
    const int fhi  = lane >> 4;

    issue_stage(0, 0);

    for (int s = 0; s < NS; s++) {
        const int p = s & 1;
        if (s + 1 < NS) {
            issue_stage(s + 1, 1 - p);
            asm volatile("cp.async.wait_group 1;");
        } else {
            asm volatile("cp.async.wait_group 0;");
        }
        __syncthreads();

        const uint32_t stb = sb + p * STAGE;
        #pragma unroll
        for (int kq = 0; kq < 2; kq++) {
            uint32_t aH[2][4], aL[2][4];
            #pragma unroll
            for (int mt = 0; mt < 2; mt++) {
                const int row = warpM * 32 + mt * 16 + frow;
                const uint32_t off = swz(row, kq * 2 + fhi);
                ldm_x4(aH[mt], stb + T_AH + off);
                ldm_x4(aL[mt], stb + T_AL + off);
            }
            uint32_t bH[4][4], bL[4][4];
            #pragma unroll
            for (int ng = 0; ng < 4; ng++) {
                const int row = warpN * 64 + ng * 16 + frow;
                const uint32_t off = swz(row, kq * 2 + fhi);
                ldm_x4(bH[ng], stb + T_BH + off);
                ldm_x4(bL[ng], stb + T_BL + off);
            }
            #pragma unroll
            for (int mt = 0; mt < 2; mt++)
                #pragma unroll
                for (int nt = 0; nt < 8; nt++) {
                    const int ng = nt >> 1, rs = nt & 1;
                    float* c = acc[mt][nt];
                    mma16816(c, aH[mt], bH[ng][rs], bH[ng][rs + 2]);
                    mma16816(c, aH[mt], bL[ng][rs], bL[ng][rs + 2]);
                    mma16816(c, aL[mt], bH[ng][rs], bH[ng][rs + 2]);
                }
        }
        __syncthreads();
    }

    // ---- epilogue: stage fp32 tile in SMEM, then coalesced global writes ----
    {
        const int PITCH = 132;
        float* st = (float*)smem;
        const int tr = lane >> 2;
        const int tc = (lane & 3) * 2;
        #pragma unroll
        for (int mt = 0; mt < 2; mt++)
            #pragma unroll
            for (int nt = 0; nt < 8; nt++) {
                const int r0 = warpM * 32 + mt * 16 + tr;
                const int c0 = warpN * 64 + nt * 8 + tc;
                st[r0 * PITCH + c0]           = acc[mt][nt][0];
                st[r0 * PITCH + c0 + 1]       = acc[mt][nt][1];
                st[(r0 + 8) * PITCH + c0]     = acc[mt][nt][2];
                st[(r0 + 8) * PITCH + c0 + 1] = acc[mt][nt][3];
            }
        __syncthreads();

        const int orow = tid >> 1;
        const int ocb  = (tid & 1) * 64;
        const float* src = st + orow * PITCH + ocb;
        const size_t cbase = (size_t)(m0 + orow) * ldc + n0 + ocb;

        if (EPI == 1) {
            #pragma unroll
            for (int j = 0; j < 64; j += 4) {
                float4 v = *(const float4*)(src + j);
                v.x *= scale; v.y *= scale; v.z *= scale; v.w *= scale;
                *(float4*)(Cf + cbase + j) = v;
            }
        } else if (EPI == 3) {
            #pragma unroll
            for (int j = 0; j < 64; j += 4) {
                float4 v = *(const float4*)(src + j);
                const float4 b = *(const float4*)(bias + n0 + ocb + j);
                v.x += b.x; v.y += b.y; v.z += b.z; v.w += b.w;
                *(float4*)(Cf + cbase + j) = v;
            }
        } else {
            #pragma unroll
            for (int j = 0; j < 64; j += 2) {
                float v0 = src[j], v1 = src[j + 1];
                if (EPI == 0) { v0 += bias[n0 + ocb + j]; v1 += bias[n0 + ocb + j + 1]; }
                const bf16 h0 = __float2bfloat16_rn(v0);
                const bf16 h1 = __float2bfloat16_rn(v1);
                const bf16 l0 = __float2bfloat16_rn(v0 - __bfloat162float(h0));
                const bf16 l1 = __float2bfloat16_rn(v1 - __bfloat162float(h1));
                const uint32_t hw = (uint32_t)__bfloat16_as_ushort(h0) |
                                    ((uint32_t)__bfloat16_as_ushort(h1) << 16);
                const uint32_t lw = (uint32_t)__bfloat16_as_ushort(l0) |
                                    ((uint32_t)__bfloat16_as_ushort(l1) << 16);
                *(uint32_t*)(Ch + cbase + j) = hw;
                *(uint32_t*)(Cl + cbase + j) = lw;
            }
        }
    }
}

// ------------------------- aux kernels --------------------------------------

__global__ __launch_bounds__(256)
void split_kernel(const float* __restrict__ x, bf16* __restrict__ h,
                  bf16* __restrict__ l)
{
    const long long i = (long long)blockIdx.x * 256 + threadIdx.x;
    const float4 v = ((const float4*)x)[i];
    bf16 hb[4], lb[4];
    const float vv[4] = {v.x, v.y, v.z, v.w};
    #pragma unroll
    for (int j = 0; j < 4; j++) {
        hb[j] = __float2bfloat16_rn(vv[j]);
        lb[j] = __float2bfloat16_rn(vv[j] - __bfloat162float(hb[j]));
    }
    uint2 hu, lu;
    hu.x = (uint32_t)__bfloat16_as_ushort(hb[0]) | ((uint32_t)__bfloat16_as_ushort(hb[1]) << 16);
    hu.y = (uint32_t)__bfloat16_as_ushort(hb[2]) | ((uint32_t)__bfloat16_as_ushort(hb[3]) << 16);
    lu.x = (uint32_t)__bfloat16_as_ushort(lb[0]) | ((uint32_t)__bfloat16_as_ushort(lb[1]) << 16);
    lu.y = (uint32_t)__bfloat16_as_ushort(lb[2]) | ((uint32_t)__bfloat16_as_ushort(lb[3]) << 16);
    ((uint2*)h)[i] = hu;
    ((uint2*)l)[i] = lu;
}

__global__ __launch_bounds__(256)
void transpose_v(const bf16* __restrict__ vh, const bf16* __restrict__ vl,
                 bf16* __restrict__ vth, bf16* __restrict__ vtl)
{
    __shared__ bf16 th[32][33];
    __shared__ bf16 tl[32][33];
    const int g = blockIdx.z;
    const int d0 = blockIdx.x * 32;
    const int k0 = blockIdx.y * 32;
    const size_t ib = (size_t)g * 131072;
    const int tx = threadIdx.x & 31;
    const int ty = threadIdx.x >> 5;
    #pragma unroll
    for (int i = 0; i < 4; i++) {
        const int k = k0 + ty + i * 8;
        th[ty + i * 8][tx] = vh[ib + (size_t)k * 128 + d0 + tx];
        tl[ty + i * 8][tx] = vl[ib + (size_t)k * 128 + d0 + tx];
    }
    __syncthreads();
    #pragma unroll
    for (int i = 0; i < 4; i++) {
        const int d = d0 + ty + i * 8;
        vth[ib + (size_t)d * 1024 + k0 + tx] = th[tx][ty + i * 8];
        vtl[ib + (size_t)d * 1024 + k0 + tx] = tl[tx][ty + i * 8];
    }
}

__global__ __launch_bounds__(256)
void softmax1024(float* __restrict__ w, bf16* __restrict__ ph, bf16* __restrict__ pl)
{
    __shared__ float smax[8];
    __shared__ float ssum[8];
    const size_t rb = (size_t)blockIdx.x * 1024;
    float* row = w + rb;
    const int tid = threadIdx.x;

    float4 v = reinterpret_cast<float4*>(row)[tid];
    float m = fmaxf(fmaxf(v.x, v.y), fmaxf(v.z, v.w));
    #pragma unroll
    for (int o = 16; o > 0; o >>= 1)
        m = fmaxf(m, __shfl_xor_sync(0xffffffffu, m, o));
    if ((tid & 31) == 0) smax[tid >> 5] = m;
    __syncthreads();
    const float bm = fmaxf(fmaxf(fmaxf(smax[0], smax[1]), fmaxf(smax[2], smax[3])),
                           fmaxf(fmaxf(smax[4], smax[5]), fmaxf(smax[6], smax[7])));
    v.x = expf(v.x - bm); v.y = expf(v.y - bm);
    v.z = expf(v.z - bm); v.w = expf(v.w - bm);
    float s = v.x + v.y + v.z + v.w;
    #pragma unroll
    for (int o = 16; o > 0; o >>= 1)
        s += __shfl_xor_sync(0xffffffffu, s, o);
    if ((tid & 31) == 0) ssum[tid >> 5] = s;
    __syncthreads();
    const float inv = 1.0f / (ssum[0] + ssum[1] + ssum[2] + ssum[3] +
                              ssum[4] + ssum[5] + ssum[6] + ssum[7]);
    v.x *= inv; v.y *= inv; v.z *= inv; v.w *= inv;
    reinterpret_cast<float4*>(row)[tid] = v;

    const float vv[4] = {v.x, v.y, v.z, v.w};
    bf16 hb[4], lb[4];
    #pragma unroll
    for (int j = 0; j < 4; j++) {
        hb[j] = __float2bfloat16_rn(vv[j]);
        lb[j] = __float2bfloat16_rn(vv[j] - __bfloat162float(hb[j]));
    }
    uint2 hu, lu;
    hu.x = (uint32_t)__bfloat16_as_ushort(hb[0]) | ((uint32_t)__bfloat16_as_ushort(hb[1]) << 16);
    hu.y = (uint32_t)__bfloat16_as_ushort(hb[2]) | ((uint32_t)__bfloat16_as_ushort(hb[3]) << 16);
    lu.x = (uint32_t)__bfloat16_as_ushort(lb[0]) | ((uint32_t)__bfloat16_as_ushort(lb[1]) << 16);
    lu.y = (uint32_t)__bfloat16_as_ushort(lb[2]) | ((uint32_t)__bfloat16_as_ushort(lb[3]) << 16);
    ((uint2*)(ph + rb))[tid] = hu;
    ((uint2*)(pl + rb))[tid] = lu;
}

// ------------------------- launcher -----------------------------------------

extern "C" void kernel_launch(void* const* d_in, const int* in_sizes, int n_in,
                              void* d_out, int out_size)
{
    (void)in_sizes; (void)n_in;
    const float* query = (const float*)d_in[0];
    const float* key   = (const float*)d_in[1];
    const float* value = (const float*)d_in[2];
    const float* Wq_w  = (const float*)d_in[3];
    const float* Wq_b  = (const float*)d_in[4];
    const float* Wk_w  = (const float*)d_in[5];
    const float* Wk_b  = (const float*)d_in[6];
    const float* Wv_w  = (const float*)d_in[7];
    const float* Wv_b  = (const float*)d_in[8];
    const float* Wo_w  = (const float*)d_in[9];
    const float* Wo_b  = (const float*)d_in[10];

    bf16 *xqh, *xql, *xkh, *xkl, *xvh, *xvl;
    bf16 *wqh, *wql, *wkh, *wkl, *wvh, *wvl, *woh, *wol;
    bf16 *Qh, *Ql, *Kh, *Kl, *Vh, *Vl, *Vth, *Vtl, *Ph, *Pl, *Ahb, *Alb;
    float* WS;
    cudaGetSymbolAddress((void**)&xqh, g_xqh); cudaGetSymbolAddress((void**)&xql, g_xql);
    cudaGetSymbolAddress((void**)&xkh, g_xkh); cudaGetSymbolAddress((void**)&xkl, g_xkl);
    cudaGetSymbolAddress((void**)&xvh, g_xvh); cudaGetSymbolAddress((void**)&xvl, g_xvl);
    cudaGetSymbolAddress((void**)&wqh, g_wqh); cudaGetSymbolAddress((void**)&wql, g_wql);
    cudaGetSymbolAddress((void**)&wkh, g_wkh); cudaGetSymbolAddress((void**)&wkl, g_wkl);
    cudaGetSymbolAddress((void**)&wvh, g_wvh); cudaGetSymbolAddress((void**)&wvl, g_wvl);
    cudaGetSymbolAddress((void**)&woh, g_woh); cudaGetSymbolAddress((void**)&wol, g_wol);
    cudaGetSymbolAddress((void**)&Qh, g_Qh);   cudaGetSymbolAddress((void**)&Ql, g_Ql);
    cudaGetSymbolAddress((void**)&Kh, g_Kh);   cudaGetSymbolAddress((void**)&Kl, g_Kl);
    cudaGetSymbolAddress((void**)&Vh, g_Vh);   cudaGetSymbolAddress((void**)&Vl, g_Vl);
    cudaGetSymbolAddress((void**)&Vth, g_Vth); cudaGetSymbolAddress((void**)&Vtl, g_Vtl);
    cudaGetSymbolAddress((void**)&Ph, g_Ph);   cudaGetSymbolAddress((void**)&Pl, g_Pl);
    cudaGetSymbolAddress((void**)&Ahb, g_Ah);  cudaGetSymbolAddress((void**)&Alb, g_Al);
    cudaGetSymbolAddress((void**)&WS, g_WS);

    float* out = (float*)d_out;
    float* weights = ((long long)out_size >= QKV_ELEMS + W_ELEMS)
                         ? out + QKV_ELEMS : WS;

    cudaFuncSetAttribute(gemm_mma<0>, cudaFuncAttributeMaxDynamicSharedMemorySize, SMEM_TOTAL);
    cudaFuncSetAttribute(gemm_mma<1>, cudaFuncAttributeMaxDynamicSharedMemorySize, SMEM_TOTAL);
    cudaFuncSetAttribute(gemm_mma<2>, cudaFuncAttributeMaxDynamicSharedMemorySize, SMEM_TOTAL);
    cudaFuncSetAttribute(gemm_mma<3>, cudaFuncAttributeMaxDynamicSharedMemorySize, SMEM_TOTAL);

    const float inv_sqrt_d = 0.022097086912079608f;  // 1/sqrt(2048)
    dim3 blk(256);

    split_kernel<<<16384, blk>>>(query, xqh, xql);
    split_kernel<<<16384, blk>>>(key,   xkh, xkl);
    split_kernel<<<16384, blk>>>(value, xvh, xvl);
    split_kernel<<<4096, blk>>>(Wq_w, wqh, wql);
    split_kernel<<<4096, blk>>>(Wk_w, wkh, wkl);
    split_kernel<<<4096, blk>>>(Wv_w, wvh, wvl);
    split_kernel<<<4096, blk>>>(Wo_w, woh, wol);

    dim3 gproj(16, 64, 1);
    gemm_mma<0><<<gproj, blk, SMEM_TOTAL>>>(xqh, xql, wqh, wql, Wq_b,
                                            nullptr, Qh, Ql,
                                            2048, 2048, 2048, 2048, 0, 0, 0, 1.f);
    gemm_mma<0><<<gproj, blk, SMEM_TOTAL>>>(xkh, xkl, wkh, wkl, Wk_b,
                                            nullptr, Kh, Kl,
                                            2048, 2048, 2048, 2048, 0, 0, 0, 1.f);
    gemm_mma<0><<<gproj, blk, SMEM_TOTAL>>>(xvh, xvl, wvh, wvl, Wv_b,
                                            nullptr, Vh, Vl,
                                            2048, 2048, 2048, 2048, 0, 0, 0, 1.f);

    transpose_v<<<dim3(4, 32, 128), blk>>>(Vh, Vl, Vth, Vtl);

    dim3 gsc(8, 8, 128);
    gemm_mma<1><<<gsc, blk, SMEM_TOTAL>>>(Qh, Ql, Kh, Kl, nullptr,
                                          weights, nullptr, nullptr,
                                          128, 128, 128, 1024,
                                          131072LL, 131072LL, 1048576LL, inv_sqrt_d);

    softmax1024<<<131072, blk>>>(weights, Ph, Pl);

    dim3 gpv(1, 8, 128);
    gemm_mma<2><<<gpv, blk, SMEM_TOTAL>>>(Ph, Pl, Vth, Vtl, nullptr,
                                          nullptr, Ahb, Alb,
                                          1024, 1024, 1024, 128,
                                          1048576LL, 131072LL, 131072LL, 1.f);

    gemm_mma<3><<<gproj, blk, SMEM_TOTAL>>>(Ahb, Alb, woh, wol, Wo_b,
                                            out, nullptr, nullptr,
                                            2048, 2048, 2048, 2048, 0, 0, 0, 1.f);
}

// round 5
// speedup vs baseline: 1.9750x; 1.1058x over previous
#include <cuda_runtime.h>
#include <cuda_bf16.h>
#include <cstdint>

// ---------------------------------------------------------------------------
// MultiHeadAttention on GB300 (sm_103a) — tensor cores via arch-portable
// mma.sync.m16n8k16 bf16 (harness PTX target is compute_103). fp32 operands
// split into bf16 hi+lo; 3 MMA terms (hh + hl + lh) in fp32 accumulators.
// R5: occupancy-2 GEMM with reg-slim inner loop, separate (proven) V
// transpose, __expf softmax. (R4's fused V-transpose epilogue used the wrong
// slab mapping — the reference head-split is a plain contiguous reshape.)
// ---------------------------------------------------------------------------

using bf16 = __nv_bfloat16;

static constexpr long long QKV_ELEMS = 8LL * 1024 * 2048;    // 16,777,216
static constexpr long long W_ELEMS   = 128LL * 1024 * 1024;  // 134,217,728
static constexpr long long WW_ELEMS  = 2048LL * 2048;        // 4,194,304

__device__ bf16 g_xqh[QKV_ELEMS], g_xql[QKV_ELEMS];
__device__ bf16 g_xkh[QKV_ELEMS], g_xkl[QKV_ELEMS];
__device__ bf16 g_xvh[QKV_ELEMS], g_xvl[QKV_ELEMS];
__device__ bf16 g_wqh[WW_ELEMS], g_wql[WW_ELEMS];
__device__ bf16 g_wkh[WW_ELEMS], g_wkl[WW_ELEMS];
__device__ bf16 g_wvh[WW_ELEMS], g_wvl[WW_ELEMS];
__device__ bf16 g_woh[WW_ELEMS], g_wol[WW_ELEMS];
__device__ bf16 g_Qh[QKV_ELEMS], g_Ql[QKV_ELEMS];
__device__ bf16 g_Kh[QKV_ELEMS], g_Kl[QKV_ELEMS];
__device__ bf16 g_Vh[QKV_ELEMS], g_Vl[QKV_ELEMS];
__device__ bf16 g_Vth[QKV_ELEMS], g_Vtl[QKV_ELEMS];
__device__ bf16 g_Ph[W_ELEMS], g_Pl[W_ELEMS];
__device__ bf16 g_Ah[QKV_ELEMS], g_Al[QKV_ELEMS];
__device__ float g_WS[W_ELEMS];

// ------------------------- asm helpers --------------------------------------

__device__ __forceinline__ uint32_t smem_u32(const void* p) {
    uint32_t a;
    asm("{ .reg .u64 t; cvta.to.shared.u64 t, %1; cvt.u32.u64 %0, t; }"
        : "=r"(a) : "l"(p));
    return a;
}

__device__ __forceinline__ void cp16(uint32_t dst, const void* src) {
    asm volatile("cp.async.cg.shared.global [%0], [%1], 16;"
                 :: "r"(dst), "l"(src));
}

__device__ __forceinline__ void ldm_x4(uint32_t* r, uint32_t addr) {
    asm volatile("ldmatrix.sync.aligned.m8n8.x4.shared.b16 {%0,%1,%2,%3}, [%4];"
                 : "=r"(r[0]), "=r"(r[1]), "=r"(r[2]), "=r"(r[3]) : "r"(addr));
}

__device__ __forceinline__ void mma16816(float* c, const uint32_t* a,
                                         uint32_t b0, uint32_t b1) {
    asm volatile(
        "mma.sync.aligned.m16n8k16.row.col.f32.bf16.bf16.f32 "
        "{%0,%1,%2,%3}, {%4,%5,%6,%7}, {%8,%9}, {%0,%1,%2,%3};"
        : "+f"(c[0]), "+f"(c[1]), "+f"(c[2]), "+f"(c[3])
        : "r"(a[0]), "r"(a[1]), "r"(a[2]), "r"(a[3]), "r"(b0), "r"(b1));
}

__device__ __forceinline__ void split2(float v0, float v1,
                                       uint32_t& hw, uint32_t& lw) {
    const bf16 h0 = __float2bfloat16_rn(v0);
    const bf16 h1 = __float2bfloat16_rn(v1);
    const bf16 l0 = __float2bfloat16_rn(v0 - __bfloat162float(h0));
    const bf16 l1 = __float2bfloat16_rn(v1 - __bfloat162float(h1));
    hw = (uint32_t)__bfloat16_as_ushort(h0) |
         ((uint32_t)__bfloat16_as_ushort(h1) << 16);
    lw = (uint32_t)__bfloat16_as_ushort(l0) |
         ((uint32_t)__bfloat16_as_ushort(l1) << 16);
}

// ------------------------- GEMM ---------------------------------------------
// NT: C[m,n] = sum_k A[m,k] * B[n,k], A/B split bf16 (hi, lo), K-major.
// EPI: 0 = split-bf16 + bias, 1 = f32 * scale, 2 = split-bf16, 3 = f32 + bias

#define STAGE 32768
#define T_AH 0
#define T_AL 8192
#define T_BH 16384
#define T_BL 24576
#define SMEM_TOTAL 69632   // max(2*STAGE, 128*132*4 epilogue staging)

__device__ __forceinline__ uint32_t swz(int row, int cq) {
    return (uint32_t)(row * 64 + ((cq ^ ((row >> 1) & 3)) << 4));
}

template <int EPI>
__global__ __launch_bounds__(256, 2)
void gemm_mma(const bf16* __restrict__ Ah, const bf16* __restrict__ Al,
              const bf16* __restrict__ Bh, const bf16* __restrict__ Bl,
              const float* __restrict__ bias,
              float* __restrict__ Cf, bf16* __restrict__ Ch, bf16* __restrict__ Cl,
              int K, int lda, int ldb, int ldc,
              long long sA, long long sB, long long sC, float scale)
{
    extern __shared__ char smem[];
    const uint32_t sb = smem_u32(smem);
    const int tid = threadIdx.x;
    const int wid = tid >> 5;
    const int lane = tid & 31;
    const int warpM = wid >> 1;          // 0..3  (m tile 32)
    const int warpN = wid & 1;           // 0..1  (n tile 64)

    const long long z = blockIdx.z;
    Ah += z * sA; Al += z * sA;
    Bh += z * sB; Bl += z * sB;
    if (EPI == 1 || EPI == 3) Cf += z * sC; else { Ch += z * sC; Cl += z * sC; }

    const int m0 = blockIdx.y * 128;
    const int n0 = blockIdx.x * 128;
    const int NS = K >> 5;

    const int lrow = tid >> 1;
    const int lcq0 = (tid & 1) * 2;

    auto issue_stage = [&](int s, int buf) {
        const int k0 = s << 5;
        const uint32_t base = sb + buf * STAGE;
        #pragma unroll
        for (int t = 0; t < 2; t++) {
            const int cq = lcq0 + t;
            const uint32_t so = swz(lrow, cq);
            const size_t ga = (size_t)(m0 + lrow) * lda + k0 + cq * 8;
            const size_t gb = (size_t)(n0 + lrow) * ldb + k0 + cq * 8;
            cp16(base + T_AH + so, Ah + ga);
            cp16(base + T_AL + so, Al + ga);
            cp16(base + T_BH + so, Bh + gb);
            cp16(base + T_BL + so, Bl + gb);
        }
        asm volatile("cp.async.commit_group;");
    };

    float acc[2][8][4];
    #pragma unroll
    for (int mt = 0; mt < 2; mt++)
        #pragma unroll
        for (int nt = 0; nt < 8; nt++)
            #pragma unroll
            for (int j = 0; j < 4; j++)
                acc[mt][nt][j] = 0.f;

    const int frow = lane & 15;
    const int fhi  = lane >> 4;

    issue_stage(0, 0);

    for (int s = 0; s < NS; s++) {
        const int p = s & 1;
        if (s + 1 < NS) {
            issue_stage(s + 1, 1 - p);
            asm volatile("cp.async.wait_group 1;");
        } else {
            asm volatile("cp.async.wait_group 0;");
        }
        __syncthreads();

        const uint32_t stb = sb + p * STAGE;
        #pragma unroll
        for (int kq = 0; kq < 2; kq++) {
            uint32_t aH[2][4], aL[2][4];
            #pragma unroll
            for (int mt = 0; mt < 2; mt++) {
                const int row = warpM * 32 + mt * 16 + frow;
                const uint32_t off = swz(row, kq * 2 + fhi);
                ldm_x4(aH[mt], stb + T_AH + off);
                ldm_x4(aL[mt], stb + T_AL + off);
            }
            // process N in two 32-col halves (keeps B frags at 16 regs)
            #pragma unroll
            for (int half = 0; half < 2; half++) {
                uint32_t bH[2][4], bL[2][4];
                #pragma unroll
                for (int g = 0; g < 2; g++) {
                    const int row = warpN * 64 + (half * 2 + g) * 16 + frow;
                    const uint32_t off = swz(row, kq * 2 + fhi);
                    ldm_x4(bH[g], stb + T_BH + off);
                    ldm_x4(bL[g], stb + T_BL + off);
                }
                #pragma unroll
                for (int mt = 0; mt < 2; mt++)
                    #pragma unroll
                    for (int t4 = 0; t4 < 4; t4++) {
                        const int g = t4 >> 1, rs = t4 & 1;
                        float* c = acc[mt][half * 4 + t4];
                        mma16816(c, aH[mt], bH[g][rs], bH[g][rs + 2]);
                        mma16816(c, aH[mt], bL[g][rs], bL[g][rs + 2]);
                        mma16816(c, aL[mt], bH[g][rs], bH[g][rs + 2]);
                    }
            }
        }
        __syncthreads();
    }

    // ---- epilogue: stage fp32 tile in SMEM, then coalesced global writes ----
    {
        const int PITCH = 132;
        float* st = (float*)smem;
        const int tr = lane >> 2;
        const int tc = (lane & 3) * 2;
        #pragma unroll
        for (int mt = 0; mt < 2; mt++)
            #pragma unroll
            for (int nt = 0; nt < 8; nt++) {
                const int r0 = warpM * 32 + mt * 16 + tr;
                const int c0 = warpN * 64 + nt * 8 + tc;
                st[r0 * PITCH + c0]           = acc[mt][nt][0];
                st[r0 * PITCH + c0 + 1]       = acc[mt][nt][1];
                st[(r0 + 8) * PITCH + c0]     = acc[mt][nt][2];
                st[(r0 + 8) * PITCH + c0 + 1] = acc[mt][nt][3];
            }
        __syncthreads();

        const int orow = tid >> 1;
        const int ocb  = (tid & 1) * 64;
        const float* src = st + orow * PITCH + ocb;
        const size_t cbase = (size_t)(m0 + orow) * ldc + n0 + ocb;

        if (EPI == 1) {
            #pragma unroll
            for (int j = 0; j < 64; j += 4) {
                float4 v = *(const float4*)(src + j);
                v.x *= scale; v.y *= scale; v.z *= scale; v.w *= scale;
                *(float4*)(Cf + cbase + j) = v;
            }
        } else if (EPI == 3) {
            #pragma unroll
            for (int j = 0; j < 64; j += 4) {
                float4 v = *(const float4*)(src + j);
                const float4 b = *(const float4*)(bias + n0 + ocb + j);
                v.x += b.x; v.y += b.y; v.z += b.z; v.w += b.w;
                *(float4*)(Cf + cbase + j) = v;
            }
        } else {
            #pragma unroll
            for (int j = 0; j < 64; j += 2) {
                float v0 = src[j], v1 = src[j + 1];
                if (EPI == 0) {
                    v0 += bias[n0 + ocb + j];
                    v1 += bias[n0 + ocb + j + 1];
                }
                uint32_t hw, lw;
                split2(v0, v1, hw, lw);
                *(uint32_t*)(Ch + cbase + j) = hw;
                *(uint32_t*)(Cl + cbase + j) = lw;
            }
        }
    }
}

// ------------------------- aux kernels --------------------------------------

__global__ __launch_bounds__(256)
void split_kernel(const float* __restrict__ x, bf16* __restrict__ h,
                  bf16* __restrict__ l)
{
    const long long i = (long long)blockIdx.x * 256 + threadIdx.x;
    const float4 v = ((const float4*)x)[i];
    uint2 hu, lu;
    split2(v.x, v.y, hu.x, lu.x);
    split2(v.z, v.w, hu.y, lu.y);
    ((uint2*)h)[i] = hu;
    ((uint2*)l)[i] = lu;
}

// per-slab [1024,128] -> [128,1024] transpose of split bf16 V
// (slab = contiguous 131072-element block, matching the plain reshape)
__global__ __launch_bounds__(256)
void transpose_v(const bf16* __restrict__ vh, const bf16* __restrict__ vl,
                 bf16* __restrict__ vth, bf16* __restrict__ vtl)
{
    __shared__ bf16 th[32][33];
    __shared__ bf16 tl[32][33];
    const int g = blockIdx.z;
    const int d0 = blockIdx.x * 32;
    const int k0 = blockIdx.y * 32;
    const size_t ib = (size_t)g * 131072;
    const int tx = threadIdx.x & 31;
    const int ty = threadIdx.x >> 5;
    #pragma unroll
    for (int i = 0; i < 4; i++) {
        const int k = k0 + ty + i * 8;
        th[ty + i * 8][tx] = vh[ib + (size_t)k * 128 + d0 + tx];
        tl[ty + i * 8][tx] = vl[ib + (size_t)k * 128 + d0 + tx];
    }
    __syncthreads();
    #pragma unroll
    for (int i = 0; i < 4; i++) {
        const int d = d0 + ty + i * 8;
        vth[ib + (size_t)d * 1024 + k0 + tx] = th[tx][ty + i * 8];
        vtl[ib + (size_t)d * 1024 + k0 + tx] = tl[tx][ty + i * 8];
    }
}

__global__ __launch_bounds__(256)
void softmax1024(float* __restrict__ w, bf16* __restrict__ ph, bf16* __restrict__ pl)
{
    __shared__ float smax[8];
    __shared__ float ssum[8];
    const size_t rb = (size_t)blockIdx.x * 1024;
    float* row = w + rb;
    const int tid = threadIdx.x;

    float4 v = reinterpret_cast<float4*>(row)[tid];
    float m = fmaxf(fmaxf(v.x, v.y), fmaxf(v.z, v.w));
    #pragma unroll
    for (int o = 16; o > 0; o >>= 1)
        m = fmaxf(m, __shfl_xor_sync(0xffffffffu, m, o));
    if ((tid & 31) == 0) smax[tid >> 5] = m;
    __syncthreads();
    const float bm = fmaxf(fmaxf(fmaxf(smax[0], smax[1]), fmaxf(smax[2], smax[3])),
                           fmaxf(fmaxf(smax[4], smax[5]), fmaxf(smax[6], smax[7])));
    v.x = __expf(v.x - bm); v.y = __expf(v.y - bm);
    v.z = __expf(v.z - bm); v.w = __expf(v.w - bm);
    float s = v.x + v.y + v.z + v.w;
    #pragma unroll
    for (int o = 16; o > 0; o >>= 1)
        s += __shfl_xor_sync(0xffffffffu, s, o);
    if ((tid & 31) == 0) ssum[tid >> 5] = s;
    __syncthreads();
    const float inv = 1.0f / (ssum[0] + ssum[1] + ssum[2] + ssum[3] +
                              ssum[4] + ssum[5] + ssum[6] + ssum[7]);
    v.x *= inv; v.y *= inv; v.z *= inv; v.w *= inv;
    reinterpret_cast<float4*>(row)[tid] = v;

    uint2 hu, lu;
    split2(v.x, v.y, hu.x, lu.x);
    split2(v.z, v.w, hu.y, lu.y);
    ((uint2*)(ph + rb))[tid] = hu;
    ((uint2*)(pl + rb))[tid] = lu;
}

// ------------------------- launcher -----------------------------------------

extern "C" void kernel_launch(void* const* d_in, const int* in_sizes, int n_in,
                              void* d_out, int out_size)
{
    (void)in_sizes; (void)n_in;
    const float* query = (const float*)d_in[0];
    const float* key   = (const float*)d_in[1];
    const float* value = (const float*)d_in[2];
    const float* Wq_w  = (const float*)d_in[3];
    const float* Wq_b  = (const float*)d_in[4];
    const float* Wk_w  = (const float*)d_in[5];
    const float* Wk_b  = (const float*)d_in[6];
    const float* Wv_w  = (const float*)d_in[7];
    const float* Wv_b  = (const float*)d_in[8];
    const float* Wo_w  = (const float*)d_in[9];
    const float* Wo_b  = (const float*)d_in[10];

    bf16 *xqh, *xql, *xkh, *xkl, *xvh, *xvl;
    bf16 *wqh, *wql, *wkh, *wkl, *wvh, *wvl, *woh, *wol;
    bf16 *Qh, *Ql, *Kh, *Kl, *Vh, *Vl, *Vth, *Vtl, *Ph, *Pl, *Ahb, *Alb;
    float* WS;
    cudaGetSymbolAddress((void**)&xqh, g_xqh); cudaGetSymbolAddress((void**)&xql, g_xql);
    cudaGetSymbolAddress((void**)&xkh, g_xkh); cudaGetSymbolAddress((void**)&xkl, g_xkl);
    cudaGetSymbolAddress((void**)&xvh, g_xvh); cudaGetSymbolAddress((void**)&xvl, g_xvl);
    cudaGetSymbolAddress((void**)&wqh, g_wqh); cudaGetSymbolAddress((void**)&wql, g_wql);
    cudaGetSymbolAddress((void**)&wkh, g_wkh); cudaGetSymbolAddress((void**)&wkl, g_wkl);
    cudaGetSymbolAddress((void**)&wvh, g_wvh); cudaGetSymbolAddress((void**)&wvl, g_wvl);
    cudaGetSymbolAddress((void**)&woh, g_woh); cudaGetSymbolAddress((void**)&wol, g_wol);
    cudaGetSymbolAddress((void**)&Qh, g_Qh);   cudaGetSymbolAddress((void**)&Ql, g_Ql);
    cudaGetSymbolAddress((void**)&Kh, g_Kh);   cudaGetSymbolAddress((void**)&Kl, g_Kl);
    cudaGetSymbolAddress((void**)&Vh, g_Vh);   cudaGetSymbolAddress((void**)&Vl, g_Vl);
    cudaGetSymbolAddress((void**)&Vth, g_Vth); cudaGetSymbolAddress((void**)&Vtl, g_Vtl);
    cudaGetSymbolAddress((void**)&Ph, g_Ph);   cudaGetSymbolAddress((void**)&Pl, g_Pl);
    cudaGetSymbolAddress((void**)&Ahb, g_Ah);  cudaGetSymbolAddress((void**)&Alb, g_Al);
    cudaGetSymbolAddress((void**)&WS, g_WS);

    float* out = (float*)d_out;
    float* weights = ((long long)out_size >= QKV_ELEMS + W_ELEMS)
                         ? out + QKV_ELEMS : WS;

    cudaFuncSetAttribute(gemm_mma<0>, cudaFuncAttributeMaxDynamicSharedMemorySize, SMEM_TOTAL);
    cudaFuncSetAttribute(gemm_mma<1>, cudaFuncAttributeMaxDynamicSharedMemorySize, SMEM_TOTAL);
    cudaFuncSetAttribute(gemm_mma<2>, cudaFuncAttributeMaxDynamicSharedMemorySize, SMEM_TOTAL);
    cudaFuncSetAttribute(gemm_mma<3>, cudaFuncAttributeMaxDynamicSharedMemorySize, SMEM_TOTAL);

    const float inv_sqrt_d = 0.022097086912079608f;  // 1/sqrt(2048)
    dim3 blk(256);

    split_kernel<<<16384, blk>>>(query, xqh, xql);
    split_kernel<<<16384, blk>>>(key,   xkh, xkl);
    split_kernel<<<16384, blk>>>(value, xvh, xvl);
    split_kernel<<<4096, blk>>>(Wq_w, wqh, wql);
    split_kernel<<<4096, blk>>>(Wk_w, wkh, wkl);
    split_kernel<<<4096, blk>>>(Wv_w, wvh, wvl);
    split_kernel<<<4096, blk>>>(Wo_w, woh, wol);

    dim3 gproj(16, 64, 1);
    gemm_mma<0><<<gproj, blk, SMEM_TOTAL>>>(xqh, xql, wqh, wql, Wq_b,
                                            nullptr, Qh, Ql,
                                            2048, 2048, 2048, 2048, 0, 0, 0, 1.f);
    gemm_mma<0><<<gproj, blk, SMEM_TOTAL>>>(xkh, xkl, wkh, wkl, Wk_b,
                                            nullptr, Kh, Kl,
                                            2048, 2048, 2048, 2048, 0, 0, 0, 1.f);
    gemm_mma<0><<<gproj, blk, SMEM_TOTAL>>>(xvh, xvl, wvh, wvl, Wv_b,
                                            nullptr, Vh, Vl,
                                            2048, 2048, 2048, 2048, 0, 0, 0, 1.f);

    transpose_v<<<dim3(4, 32, 128), blk>>>(Vh, Vl, Vth, Vtl);

    dim3 gsc(8, 8, 128);
    gemm_mma<1><<<gsc, blk, SMEM_TOTAL>>>(Qh, Ql, Kh, Kl, nullptr,
                                          weights, nullptr, nullptr,
                                          128, 128, 128, 1024,
                                          131072LL, 131072LL, 1048576LL, inv_sqrt_d);

    softmax1024<<<131072, blk>>>(weights, Ph, Pl);

    dim3 gpv(1, 8, 128);
    gemm_mma<2><<<gpv, blk, SMEM_TOTAL>>>(Ph, Pl, Vth, Vtl, nullptr,
                                          nullptr, Ahb, Alb,
                                          1024, 1024, 1024, 128,
                                          1048576LL, 131072LL, 131072LL, 1.f);

    gemm_mma<3><<<gproj, blk, SMEM_TOTAL>>>(Ahb, Alb, woh, wol, Wo_b,
                                            out, nullptr, nullptr,
                                            2048, 2048, 2048, 2048, 0, 0, 0, 1.f);
}

// round 6
// speedup vs baseline: 2.0058x; 1.0156x over previous
#include <cuda_runtime.h>
#include <cuda_bf16.h>
#include <cstdint>

// ---------------------------------------------------------------------------
// MultiHeadAttention on GB300 (sm_103a) — tensor cores via arch-portable
// mma.sync.m16n8k16 bf16 (harness PTX target is compute_103). fp32 operands
// split into bf16 hi+lo; 3 MMA terms (hh + hl + lh) in fp32 accumulators.
// R6: 3-buffer cp.async ring with ONE __syncthreads per K-stage (prefetch
// depth 2 stages), merged split kernels (also puts a big GEMM at ncu -s 5).
// ---------------------------------------------------------------------------

using bf16 = __nv_bfloat16;

static constexpr long long QKV_ELEMS = 8LL * 1024 * 2048;    // 16,777,216
static constexpr long long W_ELEMS   = 128LL * 1024 * 1024;  // 134,217,728
static constexpr long long WW_ELEMS  = 2048LL * 2048;        // 4,194,304

__device__ bf16 g_xqh[QKV_ELEMS], g_xql[QKV_ELEMS];
__device__ bf16 g_xkh[QKV_ELEMS], g_xkl[QKV_ELEMS];
__device__ bf16 g_xvh[QKV_ELEMS], g_xvl[QKV_ELEMS];
__device__ bf16 g_wqh[WW_ELEMS], g_wql[WW_ELEMS];
__device__ bf16 g_wkh[WW_ELEMS], g_wkl[WW_ELEMS];
__device__ bf16 g_wvh[WW_ELEMS], g_wvl[WW_ELEMS];
__device__ bf16 g_woh[WW_ELEMS], g_wol[WW_ELEMS];
__device__ bf16 g_Qh[QKV_ELEMS], g_Ql[QKV_ELEMS];
__device__ bf16 g_Kh[QKV_ELEMS], g_Kl[QKV_ELEMS];
__device__ bf16 g_Vh[QKV_ELEMS], g_Vl[QKV_ELEMS];
__device__ bf16 g_Vth[QKV_ELEMS], g_Vtl[QKV_ELEMS];
__device__ bf16 g_Ph[W_ELEMS], g_Pl[W_ELEMS];
__device__ bf16 g_Ah[QKV_ELEMS], g_Al[QKV_ELEMS];
__device__ float g_WS[W_ELEMS];

// ------------------------- asm helpers --------------------------------------

__device__ __forceinline__ uint32_t smem_u32(const void* p) {
    uint32_t a;
    asm("{ .reg .u64 t; cvta.to.shared.u64 t, %1; cvt.u32.u64 %0, t; }"
        : "=r"(a) : "l"(p));
    return a;
}

__device__ __forceinline__ void cp16(uint32_t dst, const void* src) {
    asm volatile("cp.async.cg.shared.global [%0], [%1], 16;"
                 :: "r"(dst), "l"(src));
}

__device__ __forceinline__ void ldm_x4(uint32_t* r, uint32_t addr) {
    asm volatile("ldmatrix.sync.aligned.m8n8.x4.shared.b16 {%0,%1,%2,%3}, [%4];"
                 : "=r"(r[0]), "=r"(r[1]), "=r"(r[2]), "=r"(r[3]) : "r"(addr));
}

__device__ __forceinline__ void mma16816(float* c, const uint32_t* a,
                                         uint32_t b0, uint32_t b1) {
    asm volatile(
        "mma.sync.aligned.m16n8k16.row.col.f32.bf16.bf16.f32 "
        "{%0,%1,%2,%3}, {%4,%5,%6,%7}, {%8,%9}, {%0,%1,%2,%3};"
        : "+f"(c[0]), "+f"(c[1]), "+f"(c[2]), "+f"(c[3])
        : "r"(a[0]), "r"(a[1]), "r"(a[2]), "r"(a[3]), "r"(b0), "r"(b1));
}

__device__ __forceinline__ void split2(float v0, float v1,
                                       uint32_t& hw, uint32_t& lw) {
    const bf16 h0 = __float2bfloat16_rn(v0);
    const bf16 h1 = __float2bfloat16_rn(v1);
    const bf16 l0 = __float2bfloat16_rn(v0 - __bfloat162float(h0));
    const bf16 l1 = __float2bfloat16_rn(v1 - __bfloat162float(h1));
    hw = (uint32_t)__bfloat16_as_ushort(h0) |
         ((uint32_t)__bfloat16_as_ushort(h1) << 16);
    lw = (uint32_t)__bfloat16_as_ushort(l0) |
         ((uint32_t)__bfloat16_as_ushort(l1) << 16);
}

// ------------------------- GEMM ---------------------------------------------
// NT: C[m,n] = sum_k A[m,k] * B[n,k], A/B split bf16 (hi, lo), K-major.
// EPI: 0 = split-bf16 + bias, 1 = f32 * scale, 2 = split-bf16, 3 = f32 + bias

#define STAGE 32768
#define T_AH 0
#define T_AL 8192
#define T_BH 16384
#define T_BL 24576
#define SMEM_TOTAL (3 * STAGE)   // 98304; epilogue staging (67.6KB) reuses it

__device__ __forceinline__ uint32_t swz(int row, int cq) {
    return (uint32_t)(row * 64 + ((cq ^ ((row >> 1) & 3)) << 4));
}

template <int EPI>
__global__ __launch_bounds__(256, 2)
void gemm_mma(const bf16* __restrict__ Ah, const bf16* __restrict__ Al,
              const bf16* __restrict__ Bh, const bf16* __restrict__ Bl,
              const float* __restrict__ bias,
              float* __restrict__ Cf, bf16* __restrict__ Ch, bf16* __restrict__ Cl,
              int K, int lda, int ldb, int ldc,
              long long sA, long long sB, long long sC, float scale)
{
    extern __shared__ char smem[];
    const uint32_t sb = smem_u32(smem);
    const int tid = threadIdx.x;
    const int wid = tid >> 5;
    const int lane = tid & 31;
    const int warpM = wid >> 1;          // 0..3  (m tile 32)
    const int warpN = wid & 1;           // 0..1  (n tile 64)

    const long long z = blockIdx.z;
    Ah += z * sA; Al += z * sA;
    Bh += z * sB; Bl += z * sB;
    if (EPI == 1 || EPI == 3) Cf += z * sC; else { Ch += z * sC; Cl += z * sC; }

    const int m0 = blockIdx.y * 128;
    const int n0 = blockIdx.x * 128;
    const int NS = K >> 5;

    const int lrow = tid >> 1;
    const int lcq0 = (tid & 1) * 2;

    auto issue_stage = [&](int s, int buf) {
        const int k0 = s << 5;
        const uint32_t base = sb + buf * STAGE;
        #pragma unroll
        for (int t = 0; t < 2; t++) {
            const int cq = lcq0 + t;
            const uint32_t so = swz(lrow, cq);
            const size_t ga = (size_t)(m0 + lrow) * lda + k0 + cq * 8;
            const size_t gb = (size_t)(n0 + lrow) * ldb + k0 + cq * 8;
            cp16(base + T_AH + so, Ah + ga);
            cp16(base + T_AL + so, Al + ga);
            cp16(base + T_BH + so, Bh + gb);
            cp16(base + T_BL + so, Bl + gb);
        }
        asm volatile("cp.async.commit_group;");
    };

    float acc[2][8][4];
    #pragma unroll
    for (int mt = 0; mt < 2; mt++)
        #pragma unroll
        for (int nt = 0; nt < 8; nt++)
            #pragma unroll
            for (int j = 0; j < 4; j++)
                acc[mt][nt][j] = 0.f;

    const int frow = lane & 15;
    const int fhi  = lane >> 4;

    // 3-buffer ring, prefetch depth 2
    issue_stage(0, 0);
    if (NS > 1) issue_stage(1, 1);

    int buf = 0;
    for (int s = 0; s < NS; s++) {
        if (s + 1 < NS) {
            asm volatile("cp.async.wait_group 1;");
        } else {
            asm volatile("cp.async.wait_group 0;");
        }
        __syncthreads();   // publish buffer `buf`; retire buffer computed at s-1
        if (s + 2 < NS) {
            int nb = buf + 2; if (nb >= 3) nb -= 3;
            issue_stage(s + 2, nb);
        }

        const uint32_t stb = sb + buf * STAGE;
        #pragma unroll
        for (int kq = 0; kq < 2; kq++) {
            uint32_t aH[2][4], aL[2][4];
            #pragma unroll
            for (int mt = 0; mt < 2; mt++) {
                const int row = warpM * 32 + mt * 16 + frow;
                const uint32_t off = swz(row, kq * 2 + fhi);
                ldm_x4(aH[mt], stb + T_AH + off);
                ldm_x4(aL[mt], stb + T_AL + off);
            }
            #pragma unroll
            for (int half = 0; half < 2; half++) {
                uint32_t bH[2][4], bL[2][4];
                #pragma unroll
                for (int g = 0; g < 2; g++) {
                    const int row = warpN * 64 + (half * 2 + g) * 16 + frow;
                    const uint32_t off = swz(row, kq * 2 + fhi);
                    ldm_x4(bH[g], stb + T_BH + off);
                    ldm_x4(bL[g], stb + T_BL + off);
                }
                #pragma unroll
                for (int mt = 0; mt < 2; mt++)
                    #pragma unroll
                    for (int t4 = 0; t4 < 4; t4++) {
                        const int g = t4 >> 1, rs = t4 & 1;
                        float* c = acc[mt][half * 4 + t4];
                        mma16816(c, aH[mt], bH[g][rs], bH[g][rs + 2]);
                        mma16816(c, aH[mt], bL[g][rs], bL[g][rs + 2]);
                        mma16816(c, aL[mt], bH[g][rs], bH[g][rs + 2]);
                    }
            }
        }
        if (++buf == 3) buf = 0;
    }
    __syncthreads();   // all compute done before reusing smem for epilogue

    // ---- epilogue: stage fp32 tile in SMEM, then coalesced global writes ----
    {
        const int PITCH = 132;
        float* st = (float*)smem;
        const int tr = lane >> 2;
        const int tc = (lane & 3) * 2;
        #pragma unroll
        for (int mt = 0; mt < 2; mt++)
            #pragma unroll
            for (int nt = 0; nt < 8; nt++) {
                const int r0 = warpM * 32 + mt * 16 + tr;
                const int c0 = warpN * 64 + nt * 8 + tc;
                st[r0 * PITCH + c0]           = acc[mt][nt][0];
                st[r0 * PITCH + c0 + 1]       = acc[mt][nt][1];
                st[(r0 + 8) * PITCH + c0]     = acc[mt][nt][2];
                st[(r0 + 8) * PITCH + c0 + 1] = acc[mt][nt][3];
            }
        __syncthreads();

        const int orow = tid >> 1;
        const int ocb  = (tid & 1) * 64;
        const float* src = st + orow * PITCH + ocb;
        const size_t cbase = (size_t)(m0 + orow) * ldc + n0 + ocb;

        if (EPI == 1) {
            #pragma unroll
            for (int j = 0; j < 64; j += 4) {
                float4 v = *(const float4*)(src + j);
                v.x *= scale; v.y *= scale; v.z *= scale; v.w *= scale;
                *(float4*)(Cf + cbase + j) = v;
            }
        } else if (EPI == 3) {
            #pragma unroll
            for (int j = 0; j < 64; j += 4) {
                float4 v = *(const float4*)(src + j);
                const float4 b = *(const float4*)(bias + n0 + ocb + j);
                v.x += b.x; v.y += b.y; v.z += b.z; v.w += b.w;
                *(float4*)(Cf + cbase + j) = v;
            }
        } else {
            #pragma unroll
            for (int j = 0; j < 64; j += 2) {
                float v0 = src[j], v1 = src[j + 1];
                if (EPI == 0) {
                    v0 += bias[n0 + ocb + j];
                    v1 += bias[n0 + ocb + j + 1];
                }
                uint32_t hw, lw;
                split2(v0, v1, hw, lw);
                *(uint32_t*)(Ch + cbase + j) = hw;
                *(uint32_t*)(Cl + cbase + j) = lw;
            }
        }
    }
}

// ------------------------- aux kernels --------------------------------------

// grid.z selects which tensor to split (merged launch)
__global__ __launch_bounds__(256)
void split3_kernel(const float* __restrict__ x0, bf16* __restrict__ h0, bf16* __restrict__ l0,
                   const float* __restrict__ x1, bf16* __restrict__ h1, bf16* __restrict__ l1,
                   const float* __restrict__ x2, bf16* __restrict__ h2, bf16* __restrict__ l2)
{
    const float* x; bf16 *h, *l;
    if (blockIdx.z == 0)      { x = x0; h = h0; l = l0; }
    else if (blockIdx.z == 1) { x = x1; h = h1; l = l1; }
    else                      { x = x2; h = h2; l = l2; }
    const long long i = (long long)blockIdx.x * 256 + threadIdx.x;
    const float4 v = ((const float4*)x)[i];
    uint2 hu, lu;
    split2(v.x, v.y, hu.x, lu.x);
    split2(v.z, v.w, hu.y, lu.y);
    ((uint2*)h)[i] = hu;
    ((uint2*)l)[i] = lu;
}

__global__ __launch_bounds__(256)
void split4_kernel(const float* __restrict__ x0, bf16* __restrict__ h0, bf16* __restrict__ l0,
                   const float* __restrict__ x1, bf16* __restrict__ h1, bf16* __restrict__ l1,
                   const float* __restrict__ x2, bf16* __restrict__ h2, bf16* __restrict__ l2,
                   const float* __restrict__ x3, bf16* __restrict__ h3, bf16* __restrict__ l3)
{
    const float* x; bf16 *h, *l;
    if (blockIdx.z == 0)      { x = x0; h = h0; l = l0; }
    else if (blockIdx.z == 1) { x = x1; h = h1; l = l1; }
    else if (blockIdx.z == 2) { x = x2; h = h2; l = l2; }
    else                      { x = x3; h = h3; l = l3; }
    const long long i = (long long)blockIdx.x * 256 + threadIdx.x;
    const float4 v = ((const float4*)x)[i];
    uint2 hu, lu;
    split2(v.x, v.y, hu.x, lu.x);
    split2(v.z, v.w, hu.y, lu.y);
    ((uint2*)h)[i] = hu;
    ((uint2*)l)[i] = lu;
}

// per-slab [1024,128] -> [128,1024] transpose of split bf16 V
__global__ __launch_bounds__(256)
void transpose_v(const bf16* __restrict__ vh, const bf16* __restrict__ vl,
                 bf16* __restrict__ vth, bf16* __restrict__ vtl)
{
    __shared__ bf16 th[32][33];
    __shared__ bf16 tl[32][33];
    const int g = blockIdx.z;
    const int d0 = blockIdx.x * 32;
    const int k0 = blockIdx.y * 32;
    const size_t ib = (size_t)g * 131072;
    const int tx = threadIdx.x & 31;
    const int ty = threadIdx.x >> 5;
    #pragma unroll
    for (int i = 0; i < 4; i++) {
        const int k = k0 + ty + i * 8;
        th[ty + i * 8][tx] = vh[ib + (size_t)k * 128 + d0 + tx];
        tl[ty + i * 8][tx] = vl[ib + (size_t)k * 128 + d0 + tx];
    }
    __syncthreads();
    #pragma unroll
    for (int i = 0; i < 4; i++) {
        const int d = d0 + ty + i * 8;
        vth[ib + (size_t)d * 1024 + k0 + tx] = th[tx][ty + i * 8];
        vtl[ib + (size_t)d * 1024 + k0 + tx] = tl[tx][ty + i * 8];
    }
}

__global__ __launch_bounds__(256)
void softmax1024(float* __restrict__ w, bf16* __restrict__ ph, bf16* __restrict__ pl)
{
    __shared__ float smax[8];
    __shared__ float ssum[8];
    const size_t rb = (size_t)blockIdx.x * 1024;
    float* row = w + rb;
    const int tid = threadIdx.x;

    float4 v = reinterpret_cast<float4*>(row)[tid];
    float m = fmaxf(fmaxf(v.x, v.y), fmaxf(v.z, v.w));
    #pragma unroll
    for (int o = 16; o > 0; o >>= 1)
        m = fmaxf(m, __shfl_xor_sync(0xffffffffu, m, o));
    if ((tid & 31) == 0) smax[tid >> 5] = m;
    __syncthreads();
    const float bm = fmaxf(fmaxf(fmaxf(smax[0], smax[1]), fmaxf(smax[2], smax[3])),
                           fmaxf(fmaxf(smax[4], smax[5]), fmaxf(smax[6], smax[7])));
    v.x = __expf(v.x - bm); v.y = __expf(v.y - bm);
    v.z = __expf(v.z - bm); v.w = __expf(v.w - bm);
    float s = v.x + v.y + v.z + v.w;
    #pragma unroll
    for (int o = 16; o > 0; o >>= 1)
        s += __shfl_xor_sync(0xffffffffu, s, o);
    if ((tid & 31) == 0) ssum[tid >> 5] = s;
    __syncthreads();
    const float inv = 1.0f / (ssum[0] + ssum[1] + ssum[2] + ssum[3] +
                              ssum[4] + ssum[5] + ssum[6] + ssum[7]);
    v.x *= inv; v.y *= inv; v.z *= inv; v.w *= inv;
    reinterpret_cast<float4*>(row)[tid] = v;

    uint2 hu, lu;
    split2(v.x, v.y, hu.x, lu.x);
    split2(v.z, v.w, hu.y, lu.y);
    ((uint2*)(ph + rb))[tid] = hu;
    ((uint2*)(pl + rb))[tid] = lu;
}

// ------------------------- launcher -----------------------------------------

extern "C" void kernel_launch(void* const* d_in, const int* in_sizes, int n_in,
                              void* d_out, int out_size)
{
    (void)in_sizes; (void)n_in;
    const float* query = (const float*)d_in[0];
    const float* key   = (const float*)d_in[1];
    const float* value = (const float*)d_in[2];
    const float* Wq_w  = (const float*)d_in[3];
    const float* Wq_b  = (const float*)d_in[4];
    const float* Wk_w  = (const float*)d_in[5];
    const float* Wk_b  = (const float*)d_in[6];
    const float* Wv_w  = (const float*)d_in[7];
    const float* Wv_b  = (const float*)d_in[8];
    const float* Wo_w  = (const float*)d_in[9];
    const float* Wo_b  = (const float*)d_in[10];

    bf16 *xqh, *xql, *xkh, *xkl, *xvh, *xvl;
    bf16 *wqh, *wql, *wkh, *wkl, *wvh, *wvl, *woh, *wol;
    bf16 *Qh, *Ql, *Kh, *Kl, *Vh, *Vl, *Vth, *Vtl, *Ph, *Pl, *Ahb, *Alb;
    float* WS;
    cudaGetSymbolAddress((void**)&xqh, g_xqh); cudaGetSymbolAddress((void**)&xql, g_xql);
    cudaGetSymbolAddress((void**)&xkh, g_xkh); cudaGetSymbolAddress((void**)&xkl, g_xkl);
    cudaGetSymbolAddress((void**)&xvh, g_xvh); cudaGetSymbolAddress((void**)&xvl, g_xvl);
    cudaGetSymbolAddress((void**)&wqh, g_wqh); cudaGetSymbolAddress((void**)&wql, g_wql);
    cudaGetSymbolAddress((void**)&wkh, g_wkh); cudaGetSymbolAddress((void**)&wkl, g_wkl);
    cudaGetSymbolAddress((void**)&wvh, g_wvh); cudaGetSymbolAddress((void**)&wvl, g_wvl);
    cudaGetSymbolAddress((void**)&woh, g_woh); cudaGetSymbolAddress((void**)&wol, g_wol);
    cudaGetSymbolAddress((void**)&Qh, g_Qh);   cudaGetSymbolAddress((void**)&Ql, g_Ql);
    cudaGetSymbolAddress((void**)&Kh, g_Kh);   cudaGetSymbolAddress((void**)&Kl, g_Kl);
    cudaGetSymbolAddress((void**)&Vh, g_Vh);   cudaGetSymbolAddress((void**)&Vl, g_Vl);
    cudaGetSymbolAddress((void**)&Vth, g_Vth); cudaGetSymbolAddress((void**)&Vtl, g_Vtl);
    cudaGetSymbolAddress((void**)&Ph, g_Ph);   cudaGetSymbolAddress((void**)&Pl, g_Pl);
    cudaGetSymbolAddress((void**)&Ahb, g_Ah);  cudaGetSymbolAddress((void**)&Alb, g_Al);
    cudaGetSymbolAddress((void**)&WS, g_WS);

    float* out = (float*)d_out;
    float* weights = ((long long)out_size >= QKV_ELEMS + W_ELEMS)
                         ? out + QKV_ELEMS : WS;

    cudaFuncSetAttribute(gemm_mma<0>, cudaFuncAttributeMaxDynamicSharedMemorySize, SMEM_TOTAL);
    cudaFuncSetAttribute(gemm_mma<1>, cudaFuncAttributeMaxDynamicSharedMemorySize, SMEM_TOTAL);
    cudaFuncSetAttribute(gemm_mma<2>, cudaFuncAttributeMaxDynamicSharedMemorySize, SMEM_TOTAL);
    cudaFuncSetAttribute(gemm_mma<3>, cudaFuncAttributeMaxDynamicSharedMemorySize, SMEM_TOTAL);

    const float inv_sqrt_d = 0.022097086912079608f;  // 1/sqrt(2048)
    dim3 blk(256);

    // launch #0: activation splits (merged), #1: weight splits (merged)
    split3_kernel<<<dim3(16384, 1, 3), blk>>>(query, xqh, xql,
                                              key,   xkh, xkl,
                                              value, xvh, xvl);
    split4_kernel<<<dim3(4096, 1, 4), blk>>>(Wq_w, wqh, wql,
                                             Wk_w, wkh, wkl,
                                             Wv_w, wvh, wvl,
                                             Wo_w, woh, wol);

    dim3 gproj(16, 64, 1);
    // #2: V projection first so transpose can follow, keeping #5 = K proj GEMM
    gemm_mma<0><<<gproj, blk, SMEM_TOTAL>>>(xvh, xvl, wvh, wvl, Wv_b,
                                            nullptr, Vh, Vl,
                                            2048, 2048, 2048, 2048, 0, 0, 0, 1.f);
    // #3: V transpose
    transpose_v<<<dim3(4, 32, 128), blk>>>(Vh, Vl, Vth, Vtl);
    // #4: Q projection
    gemm_mma<0><<<gproj, blk, SMEM_TOTAL>>>(xqh, xql, wqh, wql, Wq_b,
                                            nullptr, Qh, Ql,
                                            2048, 2048, 2048, 2048, 0, 0, 0, 1.f);
    // #5: K projection  <-- ncu -s 5 profiles this launch
    gemm_mma<0><<<gproj, blk, SMEM_TOTAL>>>(xkh, xkl, wkh, wkl, Wk_b,
                                            nullptr, Kh, Kl,
                                            2048, 2048, 2048, 2048, 0, 0, 0, 1.f);

    dim3 gsc(8, 8, 128);
    gemm_mma<1><<<gsc, blk, SMEM_TOTAL>>>(Qh, Ql, Kh, Kl, nullptr,
                                          weights, nullptr, nullptr,
                                          128, 128, 128, 1024,
                                          131072LL, 131072LL, 1048576LL, inv_sqrt_d);

    softmax1024<<<131072, blk>>>(weights, Ph, Pl);

    dim3 gpv(1, 8, 128);
    gemm_mma<2><<<gpv, blk, SMEM_TOTAL>>>(Ph, Pl, Vth, Vtl, nullptr,
                                          nullptr, Ahb, Alb,
                                          1024, 1024, 1024, 128,
                                          1048576LL, 131072LL, 131072LL, 1.f);

    gemm_mma<3><<<gproj, blk, SMEM_TOTAL>>>(Ahb, Alb, woh, wol, Wo_b,
                                            out, nullptr, nullptr,
                                            2048, 2048, 2048, 2048, 0, 0, 0, 1.f);
}

// round 7
// speedup vs baseline: 2.5911x; 1.2918x over previous
#include <cuda_runtime.h>
#include <cuda_fp16.h>
#include <cstdint>

// ---------------------------------------------------------------------------
// MultiHeadAttention on GB300 (sm_103a) — legacy-HMMA roofline established at
// 3-term bf16 (R6 = 3.95ms ≈ analytic floor). R7: cut MMA FLOPs with fp16
// 2-term asymmetric splits: A = Ah + Al (fp16 pair, exact to 2^-22), B
// truncated to fp16 (error ~2^-11/sqrt3 ≈ 1.7e-4 per GEMM).
//   C = Ah*Bh + Al*Bh          (2 MMA terms instead of 3)
// PV stays 3-term (Ph*Vh + Pl*Vh + Ph*Vl) to protect the error budget.
// ---------------------------------------------------------------------------

using f16 = __half;

static constexpr long long QKV_ELEMS = 8LL * 1024 * 2048;    // 16,777,216
static constexpr long long W_ELEMS   = 128LL * 1024 * 1024;  // 134,217,728
static constexpr long long WW_ELEMS  = 2048LL * 2048;        // 4,194,304

__device__ f16 g_xqh[QKV_ELEMS], g_xql[QKV_ELEMS];
__device__ f16 g_xkh[QKV_ELEMS], g_xkl[QKV_ELEMS];
__device__ f16 g_xvh[QKV_ELEMS], g_xvl[QKV_ELEMS];
__device__ f16 g_wq[WW_ELEMS], g_wk[WW_ELEMS], g_wv[WW_ELEMS], g_wo[WW_ELEMS];
__device__ f16 g_Qh[QKV_ELEMS], g_Ql[QKV_ELEMS];
__device__ f16 g_Kh[QKV_ELEMS];
__device__ f16 g_Vh[QKV_ELEMS], g_Vl[QKV_ELEMS];
__device__ f16 g_Vth[QKV_ELEMS], g_Vtl[QKV_ELEMS];
__device__ f16 g_Ph[W_ELEMS], g_Pl[W_ELEMS];
__device__ f16 g_Ah[QKV_ELEMS], g_Al[QKV_ELEMS];
__device__ float g_WS[W_ELEMS];

// ------------------------- asm helpers --------------------------------------

__device__ __forceinline__ uint32_t smem_u32(const void* p) {
    uint32_t a;
    asm("{ .reg .u64 t; cvta.to.shared.u64 t, %1; cvt.u32.u64 %0, t; }"
        : "=r"(a) : "l"(p));
    return a;
}

__device__ __forceinline__ void cp16(uint32_t dst, const void* src) {
    asm volatile("cp.async.cg.shared.global [%0], [%1], 16;"
                 :: "r"(dst), "l"(src));
}

__device__ __forceinline__ void ldm_x4(uint32_t* r, uint32_t addr) {
    asm volatile("ldmatrix.sync.aligned.m8n8.x4.shared.b16 {%0,%1,%2,%3}, [%4];"
                 : "=r"(r[0]), "=r"(r[1]), "=r"(r[2]), "=r"(r[3]) : "r"(addr));
}

__device__ __forceinline__ void mma16816(float* c, const uint32_t* a,
                                         uint32_t b0, uint32_t b1) {
    asm volatile(
        "mma.sync.aligned.m16n8k16.row.col.f32.f16.f16.f32 "
        "{%0,%1,%2,%3}, {%4,%5,%6,%7}, {%8,%9}, {%0,%1,%2,%3};"
        : "+f"(c[0]), "+f"(c[1]), "+f"(c[2]), "+f"(c[3])
        : "r"(a[0]), "r"(a[1]), "r"(a[2]), "r"(a[3]), "r"(b0), "r"(b1));
}

__device__ __forceinline__ void split2h(float v0, float v1,
                                        uint32_t& hw, uint32_t& lw) {
    const f16 h0 = __float2half_rn(v0);
    const f16 h1 = __float2half_rn(v1);
    const f16 l0 = __float2half_rn(v0 - __half2float(h0));
    const f16 l1 = __float2half_rn(v1 - __half2float(h1));
    hw = (uint32_t)__half_as_ushort(h0) | ((uint32_t)__half_as_ushort(h1) << 16);
    lw = (uint32_t)__half_as_ushort(l0) | ((uint32_t)__half_as_ushort(l1) << 16);
}

__device__ __forceinline__ uint32_t round2h(float v0, float v1) {
    return (uint32_t)__half_as_ushort(__float2half_rn(v0)) |
           ((uint32_t)__half_as_ushort(__float2half_rn(v1)) << 16);
}

// ------------------------- GEMM ---------------------------------------------
// NT: C[m,n] = sum_k A[m,k] * B[n,k], K-major. A = (Ah, Al) fp16 pair,
// B = Bh fp16 (+ Bl when BLO, adding the Ah*Bl term).
// EPI: 0 split-f16 + bias | 1 f32*scale | 2 split-f16 | 3 f32+bias | 5 hi-f16+bias

#define TILE8K 8192
#define T_AH 0
#define T_AL 8192
#define T_BH 16384
#define T_BL 24576

__device__ __forceinline__ uint32_t swz(int row, int cq) {
    return (uint32_t)(row * 64 + ((cq ^ ((row >> 1) & 3)) << 4));
}

template <int EPI, bool BLO>
__global__ __launch_bounds__(256, 2)
void gemm_mma(const f16* __restrict__ Ah, const f16* __restrict__ Al,
              const f16* __restrict__ Bh, const f16* __restrict__ Bl,
              const float* __restrict__ bias,
              float* __restrict__ Cf, f16* __restrict__ Ch, f16* __restrict__ Cl,
              int K, int lda, int ldb, int ldc,
              long long sA, long long sB, long long sC, float scale)
{
    constexpr int STAGE = BLO ? 4 * TILE8K : 3 * TILE8K;
    extern __shared__ char smem[];
    const uint32_t sb = smem_u32(smem);
    const int tid = threadIdx.x;
    const int wid = tid >> 5;
    const int lane = tid & 31;
    const int warpM = wid >> 1;          // 0..3  (m tile 32)
    const int warpN = wid & 1;           // 0..1  (n tile 64)

    const long long z = blockIdx.z;
    Ah += z * sA; Al += z * sA;
    Bh += z * sB; if (BLO) Bl += z * sB;
    if (EPI == 1 || EPI == 3) Cf += z * sC;
    else { Ch += z * sC; if (EPI != 5) Cl += z * sC; }

    const int m0 = blockIdx.y * 128;
    const int n0 = blockIdx.x * 128;
    const int NS = K >> 5;

    const int lrow = tid >> 1;
    const int lcq0 = (tid & 1) * 2;

    auto issue_stage = [&](int s, int buf) {
        const int k0 = s << 5;
        const uint32_t base = sb + buf * STAGE;
        #pragma unroll
        for (int t = 0; t < 2; t++) {
            const int cq = lcq0 + t;
            const uint32_t so = swz(lrow, cq);
            const size_t ga = (size_t)(m0 + lrow) * lda + k0 + cq * 8;
            const size_t gb = (size_t)(n0 + lrow) * ldb + k0 + cq * 8;
            cp16(base + T_AH + so, Ah + ga);
            cp16(base + T_AL + so, Al + ga);
            cp16(base + T_BH + so, Bh + gb);
            if (BLO) cp16(base + T_BL + so, Bl + gb);
        }
        asm volatile("cp.async.commit_group;");
    };

    float acc[2][8][4];
    #pragma unroll
    for (int mt = 0; mt < 2; mt++)
        #pragma unroll
        for (int nt = 0; nt < 8; nt++)
            #pragma unroll
            for (int j = 0; j < 4; j++)
                acc[mt][nt][j] = 0.f;

    const int frow = lane & 15;
    const int fhi  = lane >> 4;

    // 3-buffer ring, prefetch depth 2
    issue_stage(0, 0);
    if (NS > 1) issue_stage(1, 1);

    int buf = 0;
    for (int s = 0; s < NS; s++) {
        if (s + 1 < NS) {
            asm volatile("cp.async.wait_group 1;");
        } else {
            asm volatile("cp.async.wait_group 0;");
        }
        __syncthreads();
        if (s + 2 < NS) {
            int nb = buf + 2; if (nb >= 3) nb -= 3;
            issue_stage(s + 2, nb);
        }

        const uint32_t stb = sb + buf * STAGE;
        #pragma unroll
        for (int kq = 0; kq < 2; kq++) {
            uint32_t aH[2][4], aL[2][4];
            #pragma unroll
            for (int mt = 0; mt < 2; mt++) {
                const int row = warpM * 32 + mt * 16 + frow;
                const uint32_t off = swz(row, kq * 2 + fhi);
                ldm_x4(aH[mt], stb + T_AH + off);
                ldm_x4(aL[mt], stb + T_AL + off);
            }
            #pragma unroll
            for (int half = 0; half < 2; half++) {
                uint32_t bH[2][4];
                #pragma unroll
                for (int g = 0; g < 2; g++) {
                    const int row = warpN * 64 + (half * 2 + g) * 16 + frow;
                    const uint32_t off = swz(row, kq * 2 + fhi);
                    ldm_x4(bH[g], stb + T_BH + off);
                }
                if (BLO) {
                    uint32_t bL[2][4];
                    #pragma unroll
                    for (int g = 0; g < 2; g++) {
                        const int row = warpN * 64 + (half * 2 + g) * 16 + frow;
                        const uint32_t off = swz(row, kq * 2 + fhi);
                        ldm_x4(bL[g], stb + T_BL + off);
                    }
                    #pragma unroll
                    for (int mt = 0; mt < 2; mt++)
                        #pragma unroll
                        for (int t4 = 0; t4 < 4; t4++) {
                            const int g = t4 >> 1, rs = t4 & 1;
                            float* c = acc[mt][half * 4 + t4];
                            mma16816(c, aH[mt], bH[g][rs], bH[g][rs + 2]);
                            mma16816(c, aL[mt], bH[g][rs], bH[g][rs + 2]);
                            mma16816(c, aH[mt], bL[g][rs], bL[g][rs + 2]);
                        }
                } else {
                    #pragma unroll
                    for (int mt = 0; mt < 2; mt++)
                        #pragma unroll
                        for (int t4 = 0; t4 < 4; t4++) {
                            const int g = t4 >> 1, rs = t4 & 1;
                            float* c = acc[mt][half * 4 + t4];
                            mma16816(c, aH[mt], bH[g][rs], bH[g][rs + 2]);
                            mma16816(c, aL[mt], bH[g][rs], bH[g][rs + 2]);
                        }
                }
            }
        }
        if (++buf == 3) buf = 0;
    }
    __syncthreads();

    // ---- epilogue: stage fp32 tile in SMEM, then coalesced global writes ----
    {
        const int PITCH = 132;
        float* st = (float*)smem;
        const int tr = lane >> 2;
        const int tc = (lane & 3) * 2;
        #pragma unroll
        for (int mt = 0; mt < 2; mt++)
            #pragma unroll
            for (int nt = 0; nt < 8; nt++) {
                const int r0 = warpM * 32 + mt * 16 + tr;
                const int c0 = warpN * 64 + nt * 8 + tc;
                st[r0 * PITCH + c0]           = acc[mt][nt][0];
                st[r0 * PITCH + c0 + 1]       = acc[mt][nt][1];
                st[(r0 + 8) * PITCH + c0]     = acc[mt][nt][2];
                st[(r0 + 8) * PITCH + c0 + 1] = acc[mt][nt][3];
            }
        __syncthreads();

        const int orow = tid >> 1;
        const int ocb  = (tid & 1) * 64;
        const float* src = st + orow * PITCH + ocb;
        const size_t cbase = (size_t)(m0 + orow) * ldc + n0 + ocb;

        if (EPI == 1) {
            #pragma unroll
            for (int j = 0; j < 64; j += 4) {
                float4 v = *(const float4*)(src + j);
                v.x *= scale; v.y *= scale; v.z *= scale; v.w *= scale;
                *(float4*)(Cf + cbase + j) = v;
            }
        } else if (EPI == 3) {
            #pragma unroll
            for (int j = 0; j < 64; j += 4) {
                float4 v = *(const float4*)(src + j);
                const float4 b = *(const float4*)(bias + n0 + ocb + j);
                v.x += b.x; v.y += b.y; v.z += b.z; v.w += b.w;
                *(float4*)(Cf + cbase + j) = v;
            }
        } else if (EPI == 5) {
            #pragma unroll
            for (int j = 0; j < 64; j += 2) {
                const float v0 = src[j] + bias[n0 + ocb + j];
                const float v1 = src[j + 1] + bias[n0 + ocb + j + 1];
                *(uint32_t*)(Ch + cbase + j) = round2h(v0, v1);
            }
        } else {
            #pragma unroll
            for (int j = 0; j < 64; j += 2) {
                float v0 = src[j], v1 = src[j + 1];
                if (EPI == 0) {
                    v0 += bias[n0 + ocb + j];
                    v1 += bias[n0 + ocb + j + 1];
                }
                uint32_t hw, lw;
                split2h(v0, v1, hw, lw);
                *(uint32_t*)(Ch + cbase + j) = hw;
                *(uint32_t*)(Cl + cbase + j) = lw;
            }
        }
    }
}

// ------------------------- aux kernels --------------------------------------

// activation split (q,k,v merged via grid.z): fp32 -> fp16 hi+lo
__global__ __launch_bounds__(256)
void split3_kernel(const float* __restrict__ x0, f16* __restrict__ h0, f16* __restrict__ l0,
                   const float* __restrict__ x1, f16* __restrict__ h1, f16* __restrict__ l1,
                   const float* __restrict__ x2, f16* __restrict__ h2, f16* __restrict__ l2)
{
    const float* x; f16 *h, *l;
    if (blockIdx.z == 0)      { x = x0; h = h0; l = l0; }
    else if (blockIdx.z == 1) { x = x1; h = h1; l = l1; }
    else                      { x = x2; h = h2; l = l2; }
    const long long i = (long long)blockIdx.x * 256 + threadIdx.x;
    const float4 v = ((const float4*)x)[i];
    uint2 hu, lu;
    split2h(v.x, v.y, hu.x, lu.x);
    split2h(v.z, v.w, hu.y, lu.y);
    ((uint2*)h)[i] = hu;
    ((uint2*)l)[i] = lu;
}

// weight rounding (4 tensors merged): fp32 -> fp16 (hi only)
__global__ __launch_bounds__(256)
void round4_kernel(const float* __restrict__ x0, f16* __restrict__ h0,
                   const float* __restrict__ x1, f16* __restrict__ h1,
                   const float* __restrict__ x2, f16* __restrict__ h2,
                   const float* __restrict__ x3, f16* __restrict__ h3)
{
    const float* x; f16* h;
    if (blockIdx.z == 0)      { x = x0; h = h0; }
    else if (blockIdx.z == 1) { x = x1; h = h1; }
    else if (blockIdx.z == 2) { x = x2; h = h2; }
    else                      { x = x3; h = h3; }
    const long long i = (long long)blockIdx.x * 256 + threadIdx.x;
    const float4 v = ((const float4*)x)[i];
    uint2 hu;
    hu.x = round2h(v.x, v.y);
    hu.y = round2h(v.z, v.w);
    ((uint2*)h)[i] = hu;
}

// per-slab [1024,128] -> [128,1024] transpose of split fp16 V
__global__ __launch_bounds__(256)
void transpose_v(const f16* __restrict__ vh, const f16* __restrict__ vl,
                 f16* __restrict__ vth, f16* __restrict__ vtl)
{
    __shared__ f16 th[32][33];
    __shared__ f16 tl[32][33];
    const int g = blockIdx.z;
    const int d0 = blockIdx.x * 32;
    const int k0 = blockIdx.y * 32;
    const size_t ib = (size_t)g * 131072;
    const int tx = threadIdx.x & 31;
    const int ty = threadIdx.x >> 5;
    #pragma unroll
    for (int i = 0; i < 4; i++) {
        const int k = k0 + ty + i * 8;
        th[ty + i * 8][tx] = vh[ib + (size_t)k * 128 + d0 + tx];
        tl[ty + i * 8][tx] = vl[ib + (size_t)k * 128 + d0 + tx];
    }
    __syncthreads();
    #pragma unroll
    for (int i = 0; i < 4; i++) {
        const int d = d0 + ty + i * 8;
        vth[ib + (size_t)d * 1024 + k0 + tx] = th[tx][ty + i * 8];
        vtl[ib + (size_t)d * 1024 + k0 + tx] = tl[tx][ty + i * 8];
    }
}

__global__ __launch_bounds__(256)
void softmax1024(float* __restrict__ w, f16* __restrict__ ph, f16* __restrict__ pl)
{
    __shared__ float smax[8];
    __shared__ float ssum[8];
    const size_t rb = (size_t)blockIdx.x * 1024;
    float* row = w + rb;
    const int tid = threadIdx.x;

    float4 v = reinterpret_cast<float4*>(row)[tid];
    float m = fmaxf(fmaxf(v.x, v.y), fmaxf(v.z, v.w));
    #pragma unroll
    for (int o = 16; o > 0; o >>= 1)
        m = fmaxf(m, __shfl_xor_sync(0xffffffffu, m, o));
    if ((tid & 31) == 0) smax[tid >> 5] = m;
    __syncthreads();
    const float bm = fmaxf(fmaxf(fmaxf(smax[0], smax[1]), fmaxf(smax[2], smax[3])),
                           fmaxf(fmaxf(smax[4], smax[5]), fmaxf(smax[6], smax[7])));
    v.x = __expf(v.x - bm); v.y = __expf(v.y - bm);
    v.z = __expf(v.z - bm); v.w = __expf(v.w - bm);
    float s = v.x + v.y + v.z + v.w;
    #pragma unroll
    for (int o = 16; o > 0; o >>= 1)
        s += __shfl_xor_sync(0xffffffffu, s, o);
    if ((tid & 31) == 0) ssum[tid >> 5] = s;
    __syncthreads();
    const float inv = 1.0f / (ssum[0] + ssum[1] + ssum[2] + ssum[3] +
                              ssum[4] + ssum[5] + ssum[6] + ssum[7]);
    v.x *= inv; v.y *= inv; v.z *= inv; v.w *= inv;
    reinterpret_cast<float4*>(row)[tid] = v;

    uint2 hu, lu;
    split2h(v.x, v.y, hu.x, lu.x);
    split2h(v.z, v.w, hu.y, lu.y);
    ((uint2*)(ph + rb))[tid] = hu;
    ((uint2*)(pl + rb))[tid] = lu;
}

// ------------------------- launcher -----------------------------------------

extern "C" void kernel_launch(void* const* d_in, const int* in_sizes, int n_in,
                              void* d_out, int out_size)
{
    (void)in_sizes; (void)n_in;
    const float* query = (const float*)d_in[0];
    const float* key   = (const float*)d_in[1];
    const float* value = (const float*)d_in[2];
    const float* Wq_w  = (const float*)d_in[3];
    const float* Wq_b  = (const float*)d_in[4];
    const float* Wk_w  = (const float*)d_in[5];
    const float* Wk_b  = (const float*)d_in[6];
    const float* Wv_w  = (const float*)d_in[7];
    const float* Wv_b  = (const float*)d_in[8];
    const float* Wo_w  = (const float*)d_in[9];
    const float* Wo_b  = (const float*)d_in[10];

    f16 *xqh, *xql, *xkh, *xkl, *xvh, *xvl;
    f16 *wq, *wk, *wv, *wo;
    f16 *Qh, *Ql, *Kh, *Vh, *Vl, *Vth, *Vtl, *Ph, *Pl, *Ahb, *Alb;
    float* WS;
    cudaGetSymbolAddress((void**)&xqh, g_xqh); cudaGetSymbolAddress((void**)&xql, g_xql);
    cudaGetSymbolAddress((void**)&xkh, g_xkh); cudaGetSymbolAddress((void**)&xkl, g_xkl);
    cudaGetSymbolAddress((void**)&xvh, g_xvh); cudaGetSymbolAddress((void**)&xvl, g_xvl);
    cudaGetSymbolAddress((void**)&wq, g_wq);   cudaGetSymbolAddress((void**)&wk, g_wk);
    cudaGetSymbolAddress((void**)&wv, g_wv);   cudaGetSymbolAddress((void**)&wo, g_wo);
    cudaGetSymbolAddress((void**)&Qh, g_Qh);   cudaGetSymbolAddress((void**)&Ql, g_Ql);
    cudaGetSymbolAddress((void**)&Kh, g_Kh);
    cudaGetSymbolAddress((void**)&Vh, g_Vh);   cudaGetSymbolAddress((void**)&Vl, g_Vl);
    cudaGetSymbolAddress((void**)&Vth, g_Vth); cudaGetSymbolAddress((void**)&Vtl, g_Vtl);
    cudaGetSymbolAddress((void**)&Ph, g_Ph);   cudaGetSymbolAddress((void**)&Pl, g_Pl);
    cudaGetSymbolAddress((void**)&Ahb, g_Ah);  cudaGetSymbolAddress((void**)&Alb, g_Al);
    cudaGetSymbolAddress((void**)&WS, g_WS);

    float* out = (float*)d_out;
    float* weights = ((long long)out_size >= QKV_ELEMS + W_ELEMS)
                         ? out + QKV_ELEMS : WS;

    const int SM2 = 3 * 3 * TILE8K;   // 73728 (2-term stages)
    const int SM3 = 3 * 4 * TILE8K;   // 98304 (3-term stages, PV)
    cudaFuncSetAttribute(gemm_mma<0, false>, cudaFuncAttributeMaxDynamicSharedMemorySize, SM2);
    cudaFuncSetAttribute(gemm_mma<5, false>, cudaFuncAttributeMaxDynamicSharedMemorySize, SM2);
    cudaFuncSetAttribute(gemm_mma<1, false>, cudaFuncAttributeMaxDynamicSharedMemorySize, SM2);
    cudaFuncSetAttribute(gemm_mma<2, true>,  cudaFuncAttributeMaxDynamicSharedMemorySize, SM3);
    cudaFuncSetAttribute(gemm_mma<3, false>, cudaFuncAttributeMaxDynamicSharedMemorySize, SM2);

    const float inv_sqrt_d = 0.022097086912079608f;  // 1/sqrt(2048)
    dim3 blk(256);

    // #0 activation splits, #1 weight rounds
    split3_kernel<<<dim3(16384, 1, 3), blk>>>(query, xqh, xql,
                                              key,   xkh, xkl,
                                              value, xvh, xvl);
    round4_kernel<<<dim3(4096, 1, 4), blk>>>(Wq_w, wq, Wk_w, wk, Wv_w, wv, Wo_w, wo);

    dim3 gproj(16, 64, 1);
    // #2 V projection (split output), #3 transpose, #4 Q, #5 K (ncu -s 5 target)
    gemm_mma<0, false><<<gproj, blk, SM2>>>(xvh, xvl, wv, nullptr, Wv_b,
                                            nullptr, Vh, Vl,
                                            2048, 2048, 2048, 2048, 0, 0, 0, 1.f);
    transpose_v<<<dim3(4, 32, 128), blk>>>(Vh, Vl, Vth, Vtl);
    gemm_mma<0, false><<<gproj, blk, SM2>>>(xqh, xql, wq, nullptr, Wq_b,
                                            nullptr, Qh, Ql,
                                            2048, 2048, 2048, 2048, 0, 0, 0, 1.f);
    gemm_mma<5, false><<<gproj, blk, SM2>>>(xkh, xkl, wk, nullptr, Wk_b,
                                            nullptr, Kh, nullptr,
                                            2048, 2048, 2048, 2048, 0, 0, 0, 1.f);

    // scores = Q K^T * scale per contiguous slab -> fp32 weights
    dim3 gsc(8, 8, 128);
    gemm_mma<1, false><<<gsc, blk, SM2>>>(Qh, Ql, Kh, nullptr, nullptr,
                                          weights, nullptr, nullptr,
                                          128, 128, 128, 1024,
                                          131072LL, 131072LL, 1048576LL, inv_sqrt_d);

    softmax1024<<<131072, blk>>>(weights, Ph, Pl);

    // attn = P Vt^T (3-term: PhVh + PlVh + PhVl) -> split fp16
    dim3 gpv(1, 8, 128);
    gemm_mma<2, true><<<gpv, blk, SM3>>>(Ph, Pl, Vth, Vtl, nullptr,
                                         nullptr, Ahb, Alb,
                                         1024, 1024, 1024, 128,
                                         1048576LL, 131072LL, 131072LL, 1.f);

    // out = attn Wo^T + b -> fp32
    gemm_mma<3, false><<<gproj, blk, SM2>>>(Ahb, Alb, wo, nullptr, Wo_b,
                                            out, nullptr, nullptr,
                                            2048, 2048, 2048, 2048, 0, 0, 0, 1.f);
}

// round 8
// speedup vs baseline: 3.5179x; 1.3577x over previous
#include <cuda_runtime.h>
#include <cuda_fp16.h>
#include <cstdint>

// ---------------------------------------------------------------------------
// MultiHeadAttention on GB300 (sm_103a) — legacy mma.sync fp16, term-minimal.
// R8 term plan (err sources combine in quadrature, ~1.7e-4 each):
//   projections (Q,K,V,out):  1 term  (A and B truncated to fp16)
//   scores  Q·K^T:            2 terms (Q split hi+lo; K truncated)  [weights out]
//   PV      P·Vt^T:           3 terms (P split x V split)
// Measured calibration: ~143 G-MAC/ms on this mma.sync pipeline.
// ---------------------------------------------------------------------------

using f16 = __half;

static constexpr long long QKV_ELEMS = 8LL * 1024 * 2048;    // 16,777,216
static constexpr long long W_ELEMS   = 128LL * 1024 * 1024;  // 134,217,728
static constexpr long long WW_ELEMS  = 2048LL * 2048;        // 4,194,304

__device__ f16 g_xq[QKV_ELEMS], g_xk[QKV_ELEMS], g_xv[QKV_ELEMS];
__device__ f16 g_wq[WW_ELEMS], g_wk[WW_ELEMS], g_wv[WW_ELEMS], g_wo[WW_ELEMS];
__device__ f16 g_Qh[QKV_ELEMS], g_Ql[QKV_ELEMS];
__device__ f16 g_Kh[QKV_ELEMS];
__device__ f16 g_Vh[QKV_ELEMS], g_Vl[QKV_ELEMS];
__device__ f16 g_Vth[QKV_ELEMS], g_Vtl[QKV_ELEMS];
__device__ f16 g_Ph[W_ELEMS], g_Pl[W_ELEMS];
__device__ f16 g_Ah[QKV_ELEMS];
__device__ float g_WS[W_ELEMS];

// ------------------------- asm helpers --------------------------------------

__device__ __forceinline__ uint32_t smem_u32(const void* p) {
    uint32_t a;
    asm("{ .reg .u64 t; cvta.to.shared.u64 t, %1; cvt.u32.u64 %0, t; }"
        : "=r"(a) : "l"(p));
    return a;
}

__device__ __forceinline__ void cp16(uint32_t dst, const void* src) {
    asm volatile("cp.async.cg.shared.global [%0], [%1], 16;"
                 :: "r"(dst), "l"(src));
}

__device__ __forceinline__ void ldm_x4(uint32_t* r, uint32_t addr) {
    asm volatile("ldmatrix.sync.aligned.m8n8.x4.shared.b16 {%0,%1,%2,%3}, [%4];"
                 : "=r"(r[0]), "=r"(r[1]), "=r"(r[2]), "=r"(r[3]) : "r"(addr));
}

__device__ __forceinline__ void mma16816(float* c, const uint32_t* a,
                                         uint32_t b0, uint32_t b1) {
    asm volatile(
        "mma.sync.aligned.m16n8k16.row.col.f32.f16.f16.f32 "
        "{%0,%1,%2,%3}, {%4,%5,%6,%7}, {%8,%9}, {%0,%1,%2,%3};"
        : "+f"(c[0]), "+f"(c[1]), "+f"(c[2]), "+f"(c[3])
        : "r"(a[0]), "r"(a[1]), "r"(a[2]), "r"(a[3]), "r"(b0), "r"(b1));
}

__device__ __forceinline__ void split2h(float v0, float v1,
                                        uint32_t& hw, uint32_t& lw) {
    const f16 h0 = __float2half_rn(v0);
    const f16 h1 = __float2half_rn(v1);
    const f16 l0 = __float2half_rn(v0 - __half2float(h0));
    const f16 l1 = __float2half_rn(v1 - __half2float(h1));
    hw = (uint32_t)__half_as_ushort(h0) | ((uint32_t)__half_as_ushort(h1) << 16);
    lw = (uint32_t)__half_as_ushort(l0) | ((uint32_t)__half_as_ushort(l1) << 16);
}

__device__ __forceinline__ uint32_t round2h(float v0, float v1) {
    return (uint32_t)__half_as_ushort(__float2half_rn(v0)) |
           ((uint32_t)__half_as_ushort(__float2half_rn(v1)) << 16);
}

// ------------------------- GEMM ---------------------------------------------
// NT: C[m,n] = sum_k A[m,k] * B[n,k], K-major fp16 operands.
// TERMS: 1 = Ah*Bh | 2 = Ah*Bh + Al*Bh | 3 = Ah*Bh + Al*Bh + Ah*Bl
// EPI: 0 split-f16+bias | 1 f32*scale | 3 f32+bias | 5 hi-f16+bias | 6 hi-f16

#define TILE8K 8192

__device__ __forceinline__ uint32_t swz(int row, int cq) {
    return (uint32_t)(row * 64 + ((cq ^ ((row >> 1) & 3)) << 4));
}

template <int EPI, int TERMS>
__global__ __launch_bounds__(256, 2)
void gemm_mma(const f16* __restrict__ Ah, const f16* __restrict__ Al,
              const f16* __restrict__ Bh, const f16* __restrict__ Bl,
              const float* __restrict__ bias,
              float* __restrict__ Cf, f16* __restrict__ Ch, f16* __restrict__ Cl,
              int K, int lda, int ldb, int ldc,
              long long sA, long long sB, long long sC, float scale)
{
    constexpr int NTILES = TERMS + 1;           // tiles per stage
    constexpr int STAGE  = NTILES * TILE8K;
    constexpr uint32_t T_AH = 0;
    constexpr uint32_t T_AL = TILE8K;                               // TERMS>=2
    constexpr uint32_t T_BH = (TERMS >= 2) ? 2 * TILE8K : TILE8K;
    constexpr uint32_t T_BL = 3 * TILE8K;                           // TERMS==3

    extern __shared__ char smem[];
    const uint32_t sb = smem_u32(smem);
    const int tid = threadIdx.x;
    const int wid = tid >> 5;
    const int lane = tid & 31;
    const int warpM = wid >> 1;          // 0..3  (m tile 32)
    const int warpN = wid & 1;           // 0..1  (n tile 64)

    const long long z = blockIdx.z;
    Ah += z * sA; if (TERMS >= 2) Al += z * sA;
    Bh += z * sB; if (TERMS == 3) Bl += z * sB;
    if (EPI == 1 || EPI == 3) Cf += z * sC;
    else { Ch += z * sC; if (EPI == 0) Cl += z * sC; }

    const int m0 = blockIdx.y * 128;
    const int n0 = blockIdx.x * 128;
    const int NS = K >> 5;

    const int lrow = tid >> 1;
    const int lcq0 = (tid & 1) * 2;

    auto issue_stage = [&](int s, int buf) {
        const int k0 = s << 5;
        const uint32_t base = sb + buf * STAGE;
        #pragma unroll
        for (int t = 0; t < 2; t++) {
            const int cq = lcq0 + t;
            const uint32_t so = swz(lrow, cq);
            const size_t ga = (size_t)(m0 + lrow) * lda + k0 + cq * 8;
            const size_t gb = (size_t)(n0 + lrow) * ldb + k0 + cq * 8;
            cp16(base + T_AH + so, Ah + ga);
            if (TERMS >= 2) cp16(base + T_AL + so, Al + ga);
            cp16(base + T_BH + so, Bh + gb);
            if (TERMS == 3) cp16(base + T_BL + so, Bl + gb);
        }
        asm volatile("cp.async.commit_group;");
    };

    float acc[2][8][4];
    #pragma unroll
    for (int mt = 0; mt < 2; mt++)
        #pragma unroll
        for (int nt = 0; nt < 8; nt++)
            #pragma unroll
            for (int j = 0; j < 4; j++)
                acc[mt][nt][j] = 0.f;

    const int frow = lane & 15;
    const int fhi  = lane >> 4;

    // 3-buffer ring, prefetch depth 2
    issue_stage(0, 0);
    if (NS > 1) issue_stage(1, 1);

    int buf = 0;
    for (int s = 0; s < NS; s++) {
        if (s + 1 < NS) {
            asm volatile("cp.async.wait_group 1;");
        } else {
            asm volatile("cp.async.wait_group 0;");
        }
        __syncthreads();
        if (s + 2 < NS) {
            int nb = buf + 2; if (nb >= 3) nb -= 3;
            issue_stage(s + 2, nb);
        }

        const uint32_t stb = sb + buf * STAGE;
        #pragma unroll
        for (int kq = 0; kq < 2; kq++) {
            uint32_t aH[2][4], aL[2][4];
            #pragma unroll
            for (int mt = 0; mt < 2; mt++) {
                const int row = warpM * 32 + mt * 16 + frow;
                const uint32_t off = swz(row, kq * 2 + fhi);
                ldm_x4(aH[mt], stb + T_AH + off);
                if (TERMS >= 2) ldm_x4(aL[mt], stb + T_AL + off);
            }
            #pragma unroll
            for (int half = 0; half < 2; half++) {
                uint32_t bH[2][4];
                #pragma unroll
                for (int g = 0; g < 2; g++) {
                    const int row = warpN * 64 + (half * 2 + g) * 16 + frow;
                    const uint32_t off = swz(row, kq * 2 + fhi);
                    ldm_x4(bH[g], stb + T_BH + off);
                }
                if (TERMS == 3) {
                    uint32_t bL[2][4];
                    #pragma unroll
                    for (int g = 0; g < 2; g++) {
                        const int row = warpN * 64 + (half * 2 + g) * 16 + frow;
                        const uint32_t off = swz(row, kq * 2 + fhi);
                        ldm_x4(bL[g], stb + T_BL + off);
                    }
                    #pragma unroll
                    for (int mt = 0; mt < 2; mt++)
                        #pragma unroll
                        for (int t4 = 0; t4 < 4; t4++) {
                            const int g = t4 >> 1, rs = t4 & 1;
                            float* c = acc[mt][half * 4 + t4];
                            mma16816(c, aH[mt], bH[g][rs], bH[g][rs + 2]);
                            mma16816(c, aL[mt], bH[g][rs], bH[g][rs + 2]);
                            mma16816(c, aH[mt], bL[g][rs], bL[g][rs + 2]);
                        }
                } else {
                    #pragma unroll
                    for (int mt = 0; mt < 2; mt++)
                        #pragma unroll
                        for (int t4 = 0; t4 < 4; t4++) {
                            const int g = t4 >> 1, rs = t4 & 1;
                            float* c = acc[mt][half * 4 + t4];
                            mma16816(c, aH[mt], bH[g][rs], bH[g][rs + 2]);
                            if (TERMS >= 2)
                                mma16816(c, aL[mt], bH[g][rs], bH[g][rs + 2]);
                        }
                }
            }
        }
        if (++buf == 3) buf = 0;
    }
    __syncthreads();

    // ---- epilogue: stage fp32 tile in SMEM, then coalesced global writes ----
    {
        const int PITCH = 132;
        float* st = (float*)smem;
        const int tr = lane >> 2;
        const int tc = (lane & 3) * 2;
        #pragma unroll
        for (int mt = 0; mt < 2; mt++)
            #pragma unroll
            for (int nt = 0; nt < 8; nt++) {
                const int r0 = warpM * 32 + mt * 16 + tr;
                const int c0 = warpN * 64 + nt * 8 + tc;
                st[r0 * PITCH + c0]           = acc[mt][nt][0];
                st[r0 * PITCH + c0 + 1]       = acc[mt][nt][1];
                st[(r0 + 8) * PITCH + c0]     = acc[mt][nt][2];
                st[(r0 + 8) * PITCH + c0 + 1] = acc[mt][nt][3];
            }
        __syncthreads();

        const int orow = tid >> 1;
        const int ocb  = (tid & 1) * 64;
        const float* src = st + orow * PITCH + ocb;
        const size_t cbase = (size_t)(m0 + orow) * ldc + n0 + ocb;

        if (EPI == 1) {
            #pragma unroll
            for (int j = 0; j < 64; j += 4) {
                float4 v = *(const float4*)(src + j);
                v.x *= scale; v.y *= scale; v.z *= scale; v.w *= scale;
                *(float4*)(Cf + cbase + j) = v;
            }
        } else if (EPI == 3) {
            #pragma unroll
            for (int j = 0; j < 64; j += 4) {
                float4 v = *(const float4*)(src + j);
                const float4 b = *(const float4*)(bias + n0 + ocb + j);
                v.x += b.x; v.y += b.y; v.z += b.z; v.w += b.w;
                *(float4*)(Cf + cbase + j) = v;
            }
        } else if (EPI == 5 || EPI == 6) {
            #pragma unroll
            for (int j = 0; j < 64; j += 2) {
                float v0 = src[j], v1 = src[j + 1];
                if (EPI == 5) {
                    v0 += bias[n0 + ocb + j];
                    v1 += bias[n0 + ocb + j + 1];
                }
                *(uint32_t*)(Ch + cbase + j) = round2h(v0, v1);
            }
        } else {  // EPI == 0: split + bias
            #pragma unroll
            for (int j = 0; j < 64; j += 2) {
                const float v0 = src[j] + bias[n0 + ocb + j];
                const float v1 = src[j + 1] + bias[n0 + ocb + j + 1];
                uint32_t hw, lw;
                split2h(v0, v1, hw, lw);
                *(uint32_t*)(Ch + cbase + j) = hw;
                *(uint32_t*)(Cl + cbase + j) = lw;
            }
        }
    }
}

// ------------------------- aux kernels --------------------------------------

// fp32 -> fp16 rounding, 3 tensors merged (activations)
__global__ __launch_bounds__(256)
void round3_kernel(const float* __restrict__ x0, f16* __restrict__ h0,
                   const float* __restrict__ x1, f16* __restrict__ h1,
                   const float* __restrict__ x2, f16* __restrict__ h2)
{
    const float* x; f16* h;
    if (blockIdx.z == 0)      { x = x0; h = h0; }
    else if (blockIdx.z == 1) { x = x1; h = h1; }
    else                      { x = x2; h = h2; }
    const long long i = (long long)blockIdx.x * 256 + threadIdx.x;
    const float4 v = ((const float4*)x)[i];
    uint2 hu;
    hu.x = round2h(v.x, v.y);
    hu.y = round2h(v.z, v.w);
    ((uint2*)h)[i] = hu;
}

// fp32 -> fp16 rounding, 4 tensors merged (weights)
__global__ __launch_bounds__(256)
void round4_kernel(const float* __restrict__ x0, f16* __restrict__ h0,
                   const float* __restrict__ x1, f16* __restrict__ h1,
                   const float* __restrict__ x2, f16* __restrict__ h2,
                   const float* __restrict__ x3, f16* __restrict__ h3)
{
    const float* x; f16* h;
    if (blockIdx.z == 0)      { x = x0; h = h0; }
    else if (blockIdx.z == 1) { x = x1; h = h1; }
    else if (blockIdx.z == 2) { x = x2; h = h2; }
    else                      { x = x3; h = h3; }
    const long long i = (long long)blockIdx.x * 256 + threadIdx.x;
    const float4 v = ((const float4*)x)[i];
    uint2 hu;
    hu.x = round2h(v.x, v.y);
    hu.y = round2h(v.z, v.w);
    ((uint2*)h)[i] = hu;
}

// per-slab [1024,128] -> [128,1024] transpose of split fp16 V
__global__ __launch_bounds__(256)
void transpose_v(const f16* __restrict__ vh, const f16* __restrict__ vl,
                 f16* __restrict__ vth, f16* __restrict__ vtl)
{
    __shared__ f16 th[32][33];
    __shared__ f16 tl[32][33];
    const int g = blockIdx.z;
    const int d0 = blockIdx.x * 32;
    const int k0 = blockIdx.y * 32;
    const size_t ib = (size_t)g * 131072;
    const int tx = threadIdx.x & 31;
    const int ty = threadIdx.x >> 5;
    #pragma unroll
    for (int i = 0; i < 4; i++) {
        const int k = k0 + ty + i * 8;
        th[ty + i * 8][tx] = vh[ib + (size_t)k * 128 + d0 + tx];
        tl[ty + i * 8][tx] = vl[ib + (size_t)k * 128 + d0 + tx];
    }
    __syncthreads();
    #pragma unroll
    for (int i = 0; i < 4; i++) {
        const int d = d0 + ty + i * 8;
        vth[ib + (size_t)d * 1024 + k0 + tx] = th[tx][ty + i * 8];
        vtl[ib + (size_t)d * 1024 + k0 + tx] = tl[tx][ty + i * 8];
    }
}

__global__ __launch_bounds__(256)
void softmax1024(float* __restrict__ w, f16* __restrict__ ph, f16* __restrict__ pl)
{
    __shared__ float smax[8];
    __shared__ float ssum[8];
    const size_t rb = (size_t)blockIdx.x * 1024;
    float* row = w + rb;
    const int tid = threadIdx.x;

    float4 v = reinterpret_cast<float4*>(row)[tid];
    float m = fmaxf(fmaxf(v.x, v.y), fmaxf(v.z, v.w));
    #pragma unroll
    for (int o = 16; o > 0; o >>= 1)
        m = fmaxf(m, __shfl_xor_sync(0xffffffffu, m, o));
    if ((tid & 31) == 0) smax[tid >> 5] = m;
    __syncthreads();
    const float bm = fmaxf(fmaxf(fmaxf(smax[0], smax[1]), fmaxf(smax[2], smax[3])),
                           fmaxf(fmaxf(smax[4], smax[5]), fmaxf(smax[6], smax[7])));
    v.x = __expf(v.x - bm); v.y = __expf(v.y - bm);
    v.z = __expf(v.z - bm); v.w = __expf(v.w - bm);
    float s = v.x + v.y + v.z + v.w;
    #pragma unroll
    for (int o = 16; o > 0; o >>= 1)
        s += __shfl_xor_sync(0xffffffffu, s, o);
    if ((tid & 31) == 0) ssum[tid >> 5] = s;
    __syncthreads();
    const float inv = 1.0f / (ssum[0] + ssum[1] + ssum[2] + ssum[3] +
                              ssum[4] + ssum[5] + ssum[6] + ssum[7]);
    v.x *= inv; v.y *= inv; v.z *= inv; v.w *= inv;
    reinterpret_cast<float4*>(row)[tid] = v;

    uint2 hu, lu;
    split2h(v.x, v.y, hu.x, lu.x);
    split2h(v.z, v.w, hu.y, lu.y);
    ((uint2*)(ph + rb))[tid] = hu;
    ((uint2*)(pl + rb))[tid] = lu;
}

// ------------------------- launcher -----------------------------------------

extern "C" void kernel_launch(void* const* d_in, const int* in_sizes, int n_in,
                              void* d_out, int out_size)
{
    (void)in_sizes; (void)n_in;
    const float* query = (const float*)d_in[0];
    const float* key   = (const float*)d_in[1];
    const float* value = (const float*)d_in[2];
    const float* Wq_w  = (const float*)d_in[3];
    const float* Wq_b  = (const float*)d_in[4];
    const float* Wk_w  = (const float*)d_in[5];
    const float* Wk_b  = (const float*)d_in[6];
    const float* Wv_w  = (const float*)d_in[7];
    const float* Wv_b  = (const float*)d_in[8];
    const float* Wo_w  = (const float*)d_in[9];
    const float* Wo_b  = (const float*)d_in[10];

    f16 *xq, *xk, *xv, *wq, *wk, *wv, *wo;
    f16 *Qh, *Ql, *Kh, *Vh, *Vl, *Vth, *Vtl, *Ph, *Pl, *Ahb;
    float* WS;
    cudaGetSymbolAddress((void**)&xq, g_xq);   cudaGetSymbolAddress((void**)&xk, g_xk);
    cudaGetSymbolAddress((void**)&xv, g_xv);
    cudaGetSymbolAddress((void**)&wq, g_wq);   cudaGetSymbolAddress((void**)&wk, g_wk);
    cudaGetSymbolAddress((void**)&wv, g_wv);   cudaGetSymbolAddress((void**)&wo, g_wo);
    cudaGetSymbolAddress((void**)&Qh, g_Qh);   cudaGetSymbolAddress((void**)&Ql, g_Ql);
    cudaGetSymbolAddress((void**)&Kh, g_Kh);
    cudaGetSymbolAddress((void**)&Vh, g_Vh);   cudaGetSymbolAddress((void**)&Vl, g_Vl);
    cudaGetSymbolAddress((void**)&Vth, g_Vth); cudaGetSymbolAddress((void**)&Vtl, g_Vtl);
    cudaGetSymbolAddress((void**)&Ph, g_Ph);   cudaGetSymbolAddress((void**)&Pl, g_Pl);
    cudaGetSymbolAddress((void**)&Ahb, g_Ah);
    cudaGetSymbolAddress((void**)&WS, g_WS);

    float* out = (float*)d_out;
    float* weights = ((long long)out_size >= QKV_ELEMS + W_ELEMS)
                         ? out + QKV_ELEMS : WS;

    const int SM1 = 67584;            // 3 stages x 16KB = 48K < epilogue 67.6K
    const int SM2 = 73728;            // 3 stages x 24KB
    const int SM3 = 98304;            // 3 stages x 32KB
    cudaFuncSetAttribute(gemm_mma<0, 1>, cudaFuncAttributeMaxDynamicSharedMemorySize, SM1);
    cudaFuncSetAttribute(gemm_mma<5, 1>, cudaFuncAttributeMaxDynamicSharedMemorySize, SM1);
    cudaFuncSetAttribute(gemm_mma<3, 1>, cudaFuncAttributeMaxDynamicSharedMemorySize, SM1);
    cudaFuncSetAttribute(gemm_mma<1, 2>, cudaFuncAttributeMaxDynamicSharedMemorySize, SM2);
    cudaFuncSetAttribute(gemm_mma<6, 3>, cudaFuncAttributeMaxDynamicSharedMemorySize, SM3);

    const float inv_sqrt_d = 0.022097086912079608f;  // 1/sqrt(2048)
    dim3 blk(256);

    // #0 activation rounds, #1 weight rounds
    round3_kernel<<<dim3(16384, 1, 3), blk>>>(query, xq, key, xk, value, xv);
    round4_kernel<<<dim3(4096, 1, 4), blk>>>(Wq_w, wq, Wk_w, wk, Wv_w, wv, Wo_w, wo);

    dim3 gproj(16, 64, 1);
    // #2 V projection (split out for 3-term PV), #3 transpose, #4 Q (split out
    // for 2-term scores), #5 K (hi only)
    gemm_mma<0, 1><<<gproj, blk, SM1>>>(xv, nullptr, wv, nullptr, Wv_b,
                                        nullptr, Vh, Vl,
                                        2048, 2048, 2048, 2048, 0, 0, 0, 1.f);
    transpose_v<<<dim3(4, 32, 128), blk>>>(Vh, Vl, Vth, Vtl);
    gemm_mma<0, 1><<<gproj, blk, SM1>>>(xq, nullptr, wq, nullptr, Wq_b,
                                        nullptr, Qh, Ql,
                                        2048, 2048, 2048, 2048, 0, 0, 0, 1.f);
    gemm_mma<5, 1><<<gproj, blk, SM1>>>(xk, nullptr, wk, nullptr, Wk_b,
                                        nullptr, Kh, nullptr,
                                        2048, 2048, 2048, 2048, 0, 0, 0, 1.f);

    // scores = Q K^T * scale per contiguous slab -> fp32 weights (2-term)
    dim3 gsc(8, 8, 128);
    gemm_mma<1, 2><<<gsc, blk, SM2>>>(Qh, Ql, Kh, nullptr, nullptr,
                                      weights, nullptr, nullptr,
                                      128, 128, 128, 1024,
                                      131072LL, 131072LL, 1048576LL, inv_sqrt_d);

    softmax1024<<<131072, blk>>>(weights, Ph, Pl);

    // attn = P Vt^T (3-term) -> fp16 hi only
    dim3 gpv(1, 8, 128);
    gemm_mma<6, 3><<<gpv, blk, SM3>>>(Ph, Pl, Vth, Vtl, nullptr,
                                      nullptr, Ahb, nullptr,
                                      1024, 1024, 1024, 128,
                                      1048576LL, 131072LL, 131072LL, 1.f);

    // out = attn Wo^T + b -> fp32 (1-term)
    gemm_mma<3, 1><<<gproj, blk, SM1>>>(Ahb, nullptr, wo, nullptr, Wo_b,
                                        out, nullptr, nullptr,
                                        2048, 2048, 2048, 2048, 0, 0, 0, 1.f);
}

// round 9
// speedup vs baseline: 4.0964x; 1.1644x over previous
#include <cuda_runtime.h>
#include <cuda_fp16.h>
#include <cstdint>

// ---------------------------------------------------------------------------
// MultiHeadAttention on GB300 (sm_103a) — legacy mma.sync fp16, ALL GEMMs
// 1-term (operands truncated to fp16; error sources ~1.5-2e-4 each combine in
// quadrature, predicted total ~5e-4 < 1e-3 threshold).
// R9: fused QKV projection (one launch), fp16 scores buffer, softmax
// in-place (fp16 P) + exact fp32 weights, minimal aux traffic.
// ---------------------------------------------------------------------------

using f16 = __half;

static constexpr long long QKV_ELEMS = 8LL * 1024 * 2048;    // 16,777,216
static constexpr long long W_ELEMS   = 128LL * 1024 * 1024;  // 134,217,728
static constexpr long long WW_ELEMS  = 2048LL * 2048;        // 4,194,304

__device__ f16 g_xq[QKV_ELEMS], g_xk[QKV_ELEMS], g_xv[QKV_ELEMS];
__device__ f16 g_wq[WW_ELEMS], g_wk[WW_ELEMS], g_wv[WW_ELEMS], g_wo[WW_ELEMS];
__device__ f16 g_Qh[QKV_ELEMS], g_Kh[QKV_ELEMS], g_Vh[QKV_ELEMS];
__device__ f16 g_Vth[QKV_ELEMS];
__device__ f16 g_P[W_ELEMS];          // fp16 scores, then probabilities
__device__ f16 g_Ah[QKV_ELEMS];
__device__ float g_WS[W_ELEMS];       // fallback weights if d_out lacks tail

// ------------------------- asm helpers --------------------------------------

__device__ __forceinline__ uint32_t smem_u32(const void* p) {
    uint32_t a;
    asm("{ .reg .u64 t; cvta.to.shared.u64 t, %1; cvt.u32.u64 %0, t; }"
        : "=r"(a) : "l"(p));
    return a;
}

__device__ __forceinline__ void cp16(uint32_t dst, const void* src) {
    asm volatile("cp.async.cg.shared.global [%0], [%1], 16;"
                 :: "r"(dst), "l"(src));
}

__device__ __forceinline__ void ldm_x4(uint32_t* r, uint32_t addr) {
    asm volatile("ldmatrix.sync.aligned.m8n8.x4.shared.b16 {%0,%1,%2,%3}, [%4];"
                 : "=r"(r[0]), "=r"(r[1]), "=r"(r[2]), "=r"(r[3]) : "r"(addr));
}

__device__ __forceinline__ void mma16816(float* c, const uint32_t* a,
                                         uint32_t b0, uint32_t b1) {
    asm volatile(
        "mma.sync.aligned.m16n8k16.row.col.f32.f16.f16.f32 "
        "{%0,%1,%2,%3}, {%4,%5,%6,%7}, {%8,%9}, {%0,%1,%2,%3};"
        : "+f"(c[0]), "+f"(c[1]), "+f"(c[2]), "+f"(c[3])
        : "r"(a[0]), "r"(a[1]), "r"(a[2]), "r"(a[3]), "r"(b0), "r"(b1));
}

__device__ __forceinline__ uint32_t round2h(float v0, float v1) {
    return (uint32_t)__half_as_ushort(__float2half_rn(v0)) |
           ((uint32_t)__half_as_ushort(__float2half_rn(v1)) << 16);
}

// ------------------------- GEMM ---------------------------------------------
// NT: C[m,n] = sum_k A[m,k] * B[n,k], K-major fp16, 1 MMA term.
// EPI: 0 = fused QKV (3-way select, f16+bias out)
//      1 = f16 * scale (scores) | 2 = f16 (PV) | 3 = f32 + bias (out)

#define TILE8K 8192
#define STAGE  16384
#define SMEM_TOTAL 69632   // max(3*STAGE=48K, epilogue 128*132*4=67.6K)

__device__ __forceinline__ uint32_t swz(int row, int cq) {
    return (uint32_t)(row * 64 + ((cq ^ ((row >> 1) & 3)) << 4));
}

template <int EPI>
__global__ __launch_bounds__(256, 2)
void gemm_mma(const f16* __restrict__ A0, const f16* __restrict__ A1,
              const f16* __restrict__ A2,
              const f16* __restrict__ B0, const f16* __restrict__ B1,
              const f16* __restrict__ B2,
              const float* __restrict__ bias0, const float* __restrict__ bias1,
              const float* __restrict__ bias2,
              float* __restrict__ Cf,
              f16* __restrict__ C0, f16* __restrict__ C1, f16* __restrict__ C2,
              int K, int lda, int ldb, int ldc,
              long long sA, long long sB, long long sC, float scale)
{
    extern __shared__ char smem[];
    const uint32_t sb = smem_u32(smem);
    const int tid = threadIdx.x;
    const int wid = tid >> 5;
    const int lane = tid & 31;
    const int warpM = wid >> 1;          // 0..3 (m tile 32)
    const int warpN = wid & 1;           // 0..1 (n tile 64)

    const int m0 = blockIdx.y * 128;
    const int n0g = blockIdx.x * 128;

    // operand / output selection
    const f16* A;
    const f16* B;
    const float* bias;
    f16* Ch;
    int n0;
    if (EPI == 0) {
        const int sel = n0g >> 11;       // 0:Q 1:K 2:V
        n0 = n0g & 2047;
        A    = (sel == 0) ? A0 : (sel == 1) ? A1 : A2;
        B    = (sel == 0) ? B0 : (sel == 1) ? B1 : B2;
        bias = (sel == 0) ? bias0 : (sel == 1) ? bias1 : bias2;
        Ch   = (sel == 0) ? C0 : (sel == 1) ? C1 : C2;
    } else {
        const long long z = blockIdx.z;
        n0 = n0g;
        A = A0 + z * sA;
        B = B0 + z * sB;
        bias = bias0;
        Ch = (EPI == 3) ? nullptr : C0 + z * sC;
        if (EPI == 3) Cf += z * sC;
    }

    const int NS = K >> 5;
    const int lrow = tid >> 1;
    const int lcq0 = (tid & 1) * 2;

    auto issue_stage = [&](int s, int buf) {
        const int k0 = s << 5;
        const uint32_t base = sb + buf * STAGE;
        #pragma unroll
        for (int t = 0; t < 2; t++) {
            const int cq = lcq0 + t;
            const uint32_t so = swz(lrow, cq);
            cp16(base + so, A + (size_t)(m0 + lrow) * lda + k0 + cq * 8);
            cp16(base + TILE8K + so, B + (size_t)(n0 + lrow) * ldb + k0 + cq * 8);
        }
        asm volatile("cp.async.commit_group;");
    };

    float acc[2][8][4];
    #pragma unroll
    for (int mt = 0; mt < 2; mt++)
        #pragma unroll
        for (int nt = 0; nt < 8; nt++)
            #pragma unroll
            for (int j = 0; j < 4; j++)
                acc[mt][nt][j] = 0.f;

    const int frow = lane & 15;
    const int fhi  = lane >> 4;

    issue_stage(0, 0);
    if (NS > 1) issue_stage(1, 1);

    int buf = 0;
    for (int s = 0; s < NS; s++) {
        if (s + 1 < NS) {
            asm volatile("cp.async.wait_group 1;");
        } else {
            asm volatile("cp.async.wait_group 0;");
        }
        __syncthreads();
        if (s + 2 < NS) {
            int nb = buf + 2; if (nb >= 3) nb -= 3;
            issue_stage(s + 2, nb);
        }

        const uint32_t stb = sb + buf * STAGE;
        #pragma unroll
        for (int kq = 0; kq < 2; kq++) {
            uint32_t aH[2][4];
            #pragma unroll
            for (int mt = 0; mt < 2; mt++) {
                const int row = warpM * 32 + mt * 16 + frow;
                ldm_x4(aH[mt], stb + swz(row, kq * 2 + fhi));
            }
            #pragma unroll
            for (int half = 0; half < 2; half++) {
                uint32_t bH[2][4];
                #pragma unroll
                for (int g = 0; g < 2; g++) {
                    const int row = warpN * 64 + (half * 2 + g) * 16 + frow;
                    ldm_x4(bH[g], stb + TILE8K + swz(row, kq * 2 + fhi));
                }
                #pragma unroll
                for (int mt = 0; mt < 2; mt++)
                    #pragma unroll
                    for (int t4 = 0; t4 < 4; t4++) {
                        const int g = t4 >> 1, rs = t4 & 1;
                        mma16816(acc[mt][half * 4 + t4], aH[mt],
                                 bH[g][rs], bH[g][rs + 2]);
                    }
            }
        }
        if (++buf == 3) buf = 0;
    }
    __syncthreads();

    // ---- epilogue: stage fp32 tile in SMEM, then coalesced global writes ----
    {
        const int PITCH = 132;
        float* st = (float*)smem;
        const int tr = lane >> 2;
        const int tc = (lane & 3) * 2;
        #pragma unroll
        for (int mt = 0; mt < 2; mt++)
            #pragma unroll
            for (int nt = 0; nt < 8; nt++) {
                const int r0 = warpM * 32 + mt * 16 + tr;
                const int c0 = warpN * 64 + nt * 8 + tc;
                st[r0 * PITCH + c0]           = acc[mt][nt][0];
                st[r0 * PITCH + c0 + 1]       = acc[mt][nt][1];
                st[(r0 + 8) * PITCH + c0]     = acc[mt][nt][2];
                st[(r0 + 8) * PITCH + c0 + 1] = acc[mt][nt][3];
            }
        __syncthreads();

        const int orow = tid >> 1;
        const int ocb  = (tid & 1) * 64;
        const float* src = st + orow * PITCH + ocb;
        const size_t cbase = (size_t)(m0 + orow) * ldc + n0 + ocb;

        if (EPI == 3) {
            #pragma unroll
            for (int j = 0; j < 64; j += 4) {
                float4 v = *(const float4*)(src + j);
                const float4 b = *(const float4*)(bias + n0 + ocb + j);
                v.x += b.x; v.y += b.y; v.z += b.z; v.w += b.w;
                *(float4*)(Cf + cbase + j) = v;
            }
        } else if (EPI == 0) {
            #pragma unroll
            for (int j = 0; j < 64; j += 2) {
                const float v0 = src[j] + bias[n0 + ocb + j];
                const float v1 = src[j + 1] + bias[n0 + ocb + j + 1];
                *(uint32_t*)(Ch + cbase + j) = round2h(v0, v1);
            }
        } else if (EPI == 1) {
            #pragma unroll
            for (int j = 0; j < 64; j += 2)
                *(uint32_t*)(Ch + cbase + j) =
                    round2h(src[j] * scale, src[j + 1] * scale);
        } else {  // EPI == 2
            #pragma unroll
            for (int j = 0; j < 64; j += 2)
                *(uint32_t*)(Ch + cbase + j) = round2h(src[j], src[j + 1]);
        }
    }
}

// ------------------------- aux kernels --------------------------------------

// fp32 -> fp16 rounding, 3 tensors merged (activations)
__global__ __launch_bounds__(256)
void round3_kernel(const float* __restrict__ x0, f16* __restrict__ h0,
                   const float* __restrict__ x1, f16* __restrict__ h1,
                   const float* __restrict__ x2, f16* __restrict__ h2)
{
    const float* x; f16* h;
    if (blockIdx.z == 0)      { x = x0; h = h0; }
    else if (blockIdx.z == 1) { x = x1; h = h1; }
    else                      { x = x2; h = h2; }
    const long long i = (long long)blockIdx.x * 256 + threadIdx.x;
    const float4 v = ((const float4*)x)[i];
    uint2 hu;
    hu.x = round2h(v.x, v.y);
    hu.y = round2h(v.z, v.w);
    ((uint2*)h)[i] = hu;
}

// fp32 -> fp16 rounding, 4 tensors merged (weights)
__global__ __launch_bounds__(256)
void round4_kernel(const float* __restrict__ x0, f16* __restrict__ h0,
                   const float* __restrict__ x1, f16* __restrict__ h1,
                   const float* __restrict__ x2, f16* __restrict__ h2,
                   const float* __restrict__ x3, f16* __restrict__ h3)
{
    const float* x; f16* h;
    if (blockIdx.z == 0)      { x = x0; h = h0; }
    else if (blockIdx.z == 1) { x = x1; h = h1; }
    else if (blockIdx.z == 2) { x = x2; h = h2; }
    else                      { x = x3; h = h3; }
    const long long i = (long long)blockIdx.x * 256 + threadIdx.x;
    const float4 v = ((const float4*)x)[i];
    uint2 hu;
    hu.x = round2h(v.x, v.y);
    hu.y = round2h(v.z, v.w);
    ((uint2*)h)[i] = hu;
}

// per-slab [1024,128] -> [128,1024] transpose of fp16 V
__global__ __launch_bounds__(256)
void transpose_v(const f16* __restrict__ vh, f16* __restrict__ vth)
{
    __shared__ f16 th[32][33];
    const int g = blockIdx.z;
    const int d0 = blockIdx.x * 32;
    const int k0 = blockIdx.y * 32;
    const size_t ib = (size_t)g * 131072;
    const int tx = threadIdx.x & 31;
    const int ty = threadIdx.x >> 5;
    #pragma unroll
    for (int i = 0; i < 4; i++) {
        const int k = k0 + ty + i * 8;
        th[ty + i * 8][tx] = vh[ib + (size_t)k * 128 + d0 + tx];
    }
    __syncthreads();
    #pragma unroll
    for (int i = 0; i < 4; i++) {
        const int d = d0 + ty + i * 8;
        vth[ib + (size_t)d * 1024 + k0 + tx] = th[tx][ty + i * 8];
    }
}

// row softmax: read fp16 scores (already scaled), write fp32 weights to wf
// and rounded fp16 probabilities back in place.
__global__ __launch_bounds__(256)
void softmax1024(f16* __restrict__ p, float* __restrict__ wf)
{
    __shared__ float smax[8];
    __shared__ float ssum[8];
    const size_t rb = (size_t)blockIdx.x * 1024;
    const int tid = threadIdx.x;

    const uint2 raw = ((const uint2*)(p + rb))[tid];
    const __half2 h0 = *(const __half2*)&raw.x;
    const __half2 h1 = *(const __half2*)&raw.y;
    float v0 = __low2float(h0), v1 = __high2float(h0);
    float v2 = __low2float(h1), v3 = __high2float(h1);

    float m = fmaxf(fmaxf(v0, v1), fmaxf(v2, v3));
    #pragma unroll
    for (int o = 16; o > 0; o >>= 1)
        m = fmaxf(m, __shfl_xor_sync(0xffffffffu, m, o));
    if ((tid & 31) == 0) smax[tid >> 5] = m;
    __syncthreads();
    const float bm = fmaxf(fmaxf(fmaxf(smax[0], smax[1]), fmaxf(smax[2], smax[3])),
                           fmaxf(fmaxf(smax[4], smax[5]), fmaxf(smax[6], smax[7])));
    v0 = __expf(v0 - bm); v1 = __expf(v1 - bm);
    v2 = __expf(v2 - bm); v3 = __expf(v3 - bm);
    float s = v0 + v1 + v2 + v3;
    #pragma unroll
    for (int o = 16; o > 0; o >>= 1)
        s += __shfl_xor_sync(0xffffffffu, s, o);
    if ((tid & 31) == 0) ssum[tid >> 5] = s;
    __syncthreads();
    const float inv = 1.0f / (ssum[0] + ssum[1] + ssum[2] + ssum[3] +
                              ssum[4] + ssum[5] + ssum[6] + ssum[7]);
    v0 *= inv; v1 *= inv; v2 *= inv; v3 *= inv;

    ((float4*)(wf + rb))[tid] = make_float4(v0, v1, v2, v3);
    uint2 o2;
    o2.x = round2h(v0, v1);
    o2.y = round2h(v2, v3);
    ((uint2*)(p + rb))[tid] = o2;
}

// ------------------------- launcher -----------------------------------------

extern "C" void kernel_launch(void* const* d_in, const int* in_sizes, int n_in,
                              void* d_out, int out_size)
{
    (void)in_sizes; (void)n_in;
    const float* query = (const float*)d_in[0];
    const float* key   = (const float*)d_in[1];
    const float* value = (const float*)d_in[2];
    const float* Wq_w  = (const float*)d_in[3];
    const float* Wq_b  = (const float*)d_in[4];
    const float* Wk_w  = (const float*)d_in[5];
    const float* Wk_b  = (const float*)d_in[6];
    const float* Wv_w  = (const float*)d_in[7];
    const float* Wv_b  = (const float*)d_in[8];
    const float* Wo_w  = (const float*)d_in[9];
    const float* Wo_b  = (const float*)d_in[10];

    f16 *xq, *xk, *xv, *wq, *wk, *wv, *wo;
    f16 *Qh, *Kh, *Vh, *Vth, *P, *Ahb;
    float* WS;
    cudaGetSymbolAddress((void**)&xq, g_xq);   cudaGetSymbolAddress((void**)&xk, g_xk);
    cudaGetSymbolAddress((void**)&xv, g_xv);
    cudaGetSymbolAddress((void**)&wq, g_wq);   cudaGetSymbolAddress((void**)&wk, g_wk);
    cudaGetSymbolAddress((void**)&wv, g_wv);   cudaGetSymbolAddress((void**)&wo, g_wo);
    cudaGetSymbolAddress((void**)&Qh, g_Qh);   cudaGetSymbolAddress((void**)&Kh, g_Kh);
    cudaGetSymbolAddress((void**)&Vh, g_Vh);   cudaGetSymbolAddress((void**)&Vth, g_Vth);
    cudaGetSymbolAddress((void**)&P, g_P);     cudaGetSymbolAddress((void**)&Ahb, g_Ah);
    cudaGetSymbolAddress((void**)&WS, g_WS);

    float* out = (float*)d_out;
    float* weights = ((long long)out_size >= QKV_ELEMS + W_ELEMS)
                         ? out + QKV_ELEMS : WS;

    cudaFuncSetAttribute(gemm_mma<0>, cudaFuncAttributeMaxDynamicSharedMemorySize, SMEM_TOTAL);
    cudaFuncSetAttribute(gemm_mma<1>, cudaFuncAttributeMaxDynamicSharedMemorySize, SMEM_TOTAL);
    cudaFuncSetAttribute(gemm_mma<2>, cudaFuncAttributeMaxDynamicSharedMemorySize, SMEM_TOTAL);
    cudaFuncSetAttribute(gemm_mma<3>, cudaFuncAttributeMaxDynamicSharedMemorySize, SMEM_TOTAL);

    const float inv_sqrt_d = 0.022097086912079608f;  // 1/sqrt(2048)
    dim3 blk(256);

    // preprocessing rounds
    round3_kernel<<<dim3(16384, 1, 3), blk>>>(query, xq, key, xk, value, xv);
    round4_kernel<<<dim3(4096, 1, 4), blk>>>(Wq_w, wq, Wk_w, wk, Wv_w, wv, Wo_w, wo);

    // fused Q/K/V projections: one GEMM, x-grid selects {Q,K,V}
    gemm_mma<0><<<dim3(48, 64, 1), blk, SMEM_TOTAL>>>(
        xq, xk, xv, wq, wk, wv, Wq_b, Wk_b, Wv_b,
        nullptr, Qh, Kh, Vh,
        2048, 2048, 2048, 2048, 0, 0, 0, 1.f);

    transpose_v<<<dim3(4, 32, 128), blk>>>(Vh, Vth);

    // scores = Q K^T * scale per contiguous slab -> fp16 P buffer
    gemm_mma<1><<<dim3(8, 8, 128), blk, SMEM_TOTAL>>>(
        Qh, nullptr, nullptr, Kh, nullptr, nullptr, nullptr, nullptr, nullptr,
        nullptr, P, nullptr, nullptr,
        128, 128, 128, 1024,
        131072LL, 131072LL, 1048576LL, inv_sqrt_d);

    // softmax: fp16 in-place + fp32 weights out
    softmax1024<<<131072, blk>>>(P, weights);

    // attn = P Vt^T -> fp16
    gemm_mma<2><<<dim3(1, 8, 128), blk, SMEM_TOTAL>>>(
        P, nullptr, nullptr, Vth, nullptr, nullptr, nullptr, nullptr, nullptr,
        nullptr, Ahb, nullptr, nullptr,
        1024, 1024, 1024, 128,
        1048576LL, 131072LL, 131072LL, 1.f);

    // out = attn Wo^T + b -> fp32
    gemm_mma<3><<<dim3(16, 64, 1), blk, SMEM_TOTAL>>>(
        Ahb, nullptr, nullptr, wo, nullptr, nullptr, Wo_b, nullptr, nullptr,
        out, nullptr, nullptr, nullptr,
        2048, 2048, 2048, 2048, 0, 0, 0, 1.f);
}